// round 12
// baseline (speedup 1.0000x reference)
#include <cuda_runtime.h>
#include <stdint.h>

// Problem constants (fixed by the reference).
#define NPRE     6000
#define NPOST    2000
#define NB       94          // ceil(NPRE/64)
#define NROWS    (NB * 64)   // 6016, padded
#define HB       32768       // score histogram buckets (scores in [0,1))
#define BCAP     256         // per-bucket sort capacity
#define SCUT     (HB - 256)  // stash cut bucket
#define STASH_CAP 32768
#define SLOCAL   256         // per-block stash buffer
#define G1       48          // chunk boundary (groups)

// ---------------- persistent device scratch (static zero-init at load) ------
__device__ unsigned           g_hist[HB];   // fallback path only
__device__ unsigned           g_base[HB];   // fallback path only
__device__ int                g_thresh;     // fallback path only
__device__ int                g_nstash;
__device__ int                g_scount;     // scan block counter (self-reset)
__device__ int                g_mcount0;    // masknms phase-0 counter
__device__ int                g_mcount1;    // masknms phase-1 counter
__device__ unsigned long long g_stash[STASH_CAP];
// SoA boxes (padded rows >= NPRE are never written -> stay zero)
__device__ float              g_y1[NROWS], g_x1[NROWS], g_y2[NROWS], g_x2[NROWS];
__device__ float              g_pa[NROWS];      // 0.7f * area
__device__ float              g_scores[NROWS];
__device__ unsigned long long g_maskT[NB][NROWS];   // [col_group][row]
__device__ unsigned long long g_alive[NB];
__device__ int                g_kept[NPOST];
__device__ int                g_kcount;
__device__ int                g_done;

__device__ __forceinline__ int score_bucket(float s) {
    int b = (int)(s * 32768.0f);
    return max(0, min(HB - 1, b));
}

// ---------------- K1: scan + stash + (last block) threshold check -----------
__global__ void scan_stash_k(const float4* __restrict__ s4, int n4) {
    __shared__ unsigned long long s_stash[SLOCAL];
    __shared__ int s_scnt, s_sbase, s_last;
    __shared__ unsigned sscan[256];
    int t = threadIdx.x;                      // 256 threads
    if (t == 0) s_scnt = 0;
    __syncthreads();
    int i = blockIdx.x * blockDim.x + t;
    int stride = gridDim.x * blockDim.x;
    for (; i < n4; i += stride) {
        float4 v = s4[i];
        float e[4] = {v.x, v.y, v.z, v.w};
#pragma unroll
        for (int c = 0; c < 4; c++) {
            if (score_bucket(e[c]) >= SCUT) {
                unsigned idx = (unsigned)(4 * i + c);
                unsigned long long key =
                    ((unsigned long long)__float_as_uint(e[c]) << 32)
                  | (unsigned long long)(0xFFFFFFFFu - idx);
                int p = atomicAdd(&s_scnt, 1);
                if (p < SLOCAL) s_stash[p] = key;
                else {                        // rare overflow: direct global
                    int q = atomicAdd(&g_nstash, 1);
                    if (q < STASH_CAP) g_stash[q] = key;
                }
            }
        }
    }
    __syncthreads();
    int cnt = s_scnt; if (cnt > SLOCAL) cnt = SLOCAL;
    if (t == 0) s_sbase = (cnt > 0) ? atomicAdd(&g_nstash, cnt) : 0;
    __syncthreads();
    for (int k = t; k < cnt; k += 256) {
        int q = s_sbase + k;
        if (q < STASH_CAP) g_stash[q] = s_stash[k];
    }
    // ---- last-block-done: threshold check (+exact fallback, never taken) ---
    __threadfence();
    __syncthreads();
    if (t == 0) s_last = (atomicAdd(&g_scount, 1) == (int)gridDim.x - 1);
    __syncthreads();
    if (!s_last) return;
    if (t == 0) g_scount = 0;                 // self-reset for next replay
    int ns = atomicAdd(&g_nstash, 0);
    if (ns >= NPRE && ns <= STASH_CAP) return;  // fast path: nothing to do
    // fallback: full histogram + descending rank bases (256 threads)
    for (int k = t; k < n4; k += 256) {
        float4 v = s4[k];
        atomicAdd(&g_hist[score_bucket(v.x)], 1u);
        atomicAdd(&g_hist[score_bucket(v.y)], 1u);
        atomicAdd(&g_hist[score_bucket(v.z)], 1u);
        atomicAdd(&g_hist[score_bucket(v.w)], 1u);
    }
    __syncthreads();
    int lo = HB - (t + 1) * 128;              // t owns buckets [lo, lo+128)
    unsigned sum = 0;
    for (int b = 0; b < 128; b++) sum += g_hist[lo + b];
    sscan[t] = sum;
    __syncthreads();
    for (int off = 1; off < 256; off <<= 1) {
        unsigned v = (t >= off) ? sscan[t - off] : 0u;
        __syncthreads();
        sscan[t] += v;
        __syncthreads();
    }
    unsigned run = sscan[t] - sum;            // count strictly above this chunk
    for (int b = 127; b >= 0; --b) {
        unsigned c = g_hist[lo + b];
        g_base[lo + b] = run;
        if (run < (unsigned)NPRE && run + c >= (unsigned)NPRE) g_thresh = lo + b;
        run += c;
    }
    if (t == 255 && sscan[255] < (unsigned)NPRE) g_thresh = 0;
}

// ---------------- K2: per-bucket gather + sort + decode (fused) -------------
__global__ void sortdecode_k(const float* __restrict__ enc,
                             const float* __restrict__ anch,
                             const float* __restrict__ scores, int n) {
    __shared__ unsigned long long s[BCAP];
    __shared__ int s_cnt, s_above;
    int t = threadIdx.x;                      // 256 threads
    int ns = g_nstash;
    bool ok = (ns >= NPRE && ns <= STASH_CAP);

    if (ok) {
        int b = HB - 1 - blockIdx.x;          // gridDim.x == 256
        if (t == 0) { s_cnt = 0; s_above = 0; }
        __syncthreads();
        int above = 0;
        for (int i = t; i < ns; i += 256) {
            unsigned long long key = g_stash[i];
            int kb = score_bucket(__uint_as_float((unsigned)(key >> 32)));
            if (kb > b) above++;
            else if (kb == b) {
                int p = atomicAdd(&s_cnt, 1);
                if (p < BCAP) s[p] = key;
            }
        }
        if (above) atomicAdd(&s_above, above);
        __syncthreads();
        int base = s_above;
        int cnt = s_cnt; if (cnt > BCAP) cnt = BCAP;
        if (base >= NPRE || cnt == 0) return;
        int kmax = 1; while (kmax < cnt) kmax <<= 1;
        for (int i = t; i < kmax; i += 256) if (i >= cnt) s[i] = 0ull;
        __syncthreads();
        for (int k = 2; k <= kmax; k <<= 1) {
            for (int j = k >> 1; j > 0; j >>= 1) {
                for (int p = t; p < (kmax >> 1); p += 256) {
                    int i = ((p & ~(j - 1)) << 1) | (p & (j - 1));
                    int x = i | j;
                    unsigned long long a = s[i], bb = s[x];
                    bool desc = ((i & k) == 0);
                    if (desc ? (a < bb) : (a > bb)) { s[i] = bb; s[x] = a; }
                }
                __syncthreads();
            }
        }
        int lim = cnt;
        if (base + lim > NPRE) lim = NPRE - base;
        for (int i = t; i < lim; i += 256) {
            unsigned long long key = s[i];
            int r = base + i;
            float y1 = 0.f, x1 = 0.f, y2 = 0.f, x2 = 0.f, sc = 0.f;
            unsigned idx = 0xFFFFFFFFu - (unsigned)(key & 0xFFFFFFFFull);
            if (idx < (unsigned)n) {
                sc = __uint_as_float((unsigned)(key >> 32));
                float4 a = ((const float4*)anch)[idx];   // [y1, x1, y2, x2]
                float4 e = ((const float4*)enc)[idx];    // [ty, tx, th, tw]
                float ha = a.z - a.x, wa = a.w - a.y;
                float cya = a.x + 0.5f * ha, cxa = a.y + 0.5f * wa;
                float cy = e.x * ha + cya;
                float cx = e.y * wa + cxa;
                float h  = expf(e.z) * ha;
                float w  = expf(e.w) * wa;
                y1 = cy - 0.5f * h; x1 = cx - 0.5f * w;
                y2 = cy + 0.5f * h; x2 = cx + 0.5f * w;
            }
            g_y1[r] = y1; g_x1[r] = x1; g_y2[r] = y2; g_x2[r] = x2;
            g_pa[r] = 0.7f * (y2 - y1) * (x2 - x1);
            g_scores[r] = sc;
        }
        return;
    }

    // ---- exact fallback (never taken for this data) -------------------------
    int T = g_thresh;
    for (int b = T + (int)blockIdx.x; b < HB; b += gridDim.x) {
        unsigned base = g_base[b];
        if (base >= (unsigned)NPRE) continue;
        if (t == 0) s_cnt = 0;
        __syncthreads();
        for (int i = t; i < n; i += 256) {
            float sv = scores[i];
            if (score_bucket(sv) == b) {
                int p = atomicAdd(&s_cnt, 1);
                if (p < BCAP)
                    s[p] = ((unsigned long long)__float_as_uint(sv) << 32)
                         | (unsigned long long)(0xFFFFFFFFu - (unsigned)i);
            }
        }
        __syncthreads();
        int cnt = s_cnt; if (cnt > BCAP) cnt = BCAP;
        if (cnt == 0) { __syncthreads(); continue; }
        int kmax = 1; while (kmax < cnt) kmax <<= 1;
        for (int i = t; i < kmax; i += 256) if (i >= cnt) s[i] = 0ull;
        __syncthreads();
        for (int k = 2; k <= kmax; k <<= 1) {
            for (int j = k >> 1; j > 0; j >>= 1) {
                for (int p = t; p < (kmax >> 1); p += 256) {
                    int i = ((p & ~(j - 1)) << 1) | (p & (j - 1));
                    int x = i | j;
                    unsigned long long a = s[i], bb = s[x];
                    bool desc = ((i & k) == 0);
                    if (desc ? (a < bb) : (a > bb)) { s[i] = bb; s[x] = a; }
                }
                __syncthreads();
            }
        }
        int lim = cnt;
        if ((int)base + lim > NPRE) lim = NPRE - (int)base;
        for (int i = t; i < lim; i += 256) {
            unsigned long long key = s[i];
            int r = (int)base + i;
            float y1 = 0.f, x1 = 0.f, y2 = 0.f, x2 = 0.f, sc = 0.f;
            unsigned idx = 0xFFFFFFFFu - (unsigned)(key & 0xFFFFFFFFull);
            if (idx < (unsigned)n) {
                sc = __uint_as_float((unsigned)(key >> 32));
                float4 a = ((const float4*)anch)[idx];
                float4 e = ((const float4*)enc)[idx];
                float ha = a.z - a.x, wa = a.w - a.y;
                float cya = a.x + 0.5f * ha, cxa = a.y + 0.5f * wa;
                float cy = e.x * ha + cya;
                float cx = e.y * wa + cxa;
                float h  = expf(e.z) * ha;
                float w  = expf(e.w) * wa;
                y1 = cy - 0.5f * h; x1 = cx - 0.5f * w;
                y2 = cy + 0.5f * h; x2 = cx + 0.5f * w;
            }
            g_y1[r] = y1; g_x1[r] = x1; g_y2[r] = y2; g_x2[r] = x2;
            g_pa[r] = 0.7f * (y2 - y1) * (x2 - x1);
            g_scores[r] = sc;
        }
        __syncthreads();
    }
}

// ---------------- NMS reduce run by ONE 256-thread block --------------------
__device__ void nms_run(int g0, int g1, float* __restrict__ out) {
    __shared__ int                s_kept[NPOST];
    __shared__ unsigned long long s_alive[NB];
    __shared__ unsigned long long s_col[64];
    __shared__ unsigned long long s_cross, s_colOR, s_alivew;
    __shared__ int s_kc;
    int t = threadIdx.x;
    int kcount = g_kcount;
    for (int i = t; i < kcount; i += 256) s_kept[i] = g_kept[i];
    for (int i = t; i < NB; i += 256) s_alive[i] = g_alive[i];
    if (t == 0) { s_cross = 0ull; s_colOR = 0ull; s_alivew = 0ull; }
    __syncthreads();

    if (g1 > NB) g1 = NB;
    for (int g = g0; g < g1; ++g) {
        int base = g * 64;
        int n = NPRE - base; if (n > 64) n = 64;
        // Phase A: column words + branchless alive-masked cross-OR
        if (t < 64) {
            unsigned long long w = g_maskT[g][base + t];
            s_col[t] = w;
            if (w) atomicOr(&s_colOR, w);
        }
        {
            const unsigned long long* colgp = g_maskT[g];
            unsigned long long p = 0ull;
            int r = t;
            for (; r + 768 < base; r += 1024) {   // 4-wide for MLP
                unsigned long long a0 = colgp[r]       & (0ull - ((s_alive[(r)       >> 6] >> ((r)       & 63)) & 1ull));
                unsigned long long a1 = colgp[r + 256] & (0ull - ((s_alive[(r + 256) >> 6] >> ((r + 256) & 63)) & 1ull));
                unsigned long long a2 = colgp[r + 512] & (0ull - ((s_alive[(r + 512) >> 6] >> ((r + 512) & 63)) & 1ull));
                unsigned long long a3 = colgp[r + 768] & (0ull - ((s_alive[(r + 768) >> 6] >> ((r + 768) & 63)) & 1ull));
                p |= (a0 | a1) | (a2 | a3);
            }
            for (; r < base; r += 256)
                p |= colgp[r] & (0ull - ((s_alive[r >> 6] >> (r & 63)) & 1ull));
            if (p) atomicOr(&s_cross, p);
        }
        __syncthreads();
        // Phase B: decision
        unsigned long long cross = s_cross;
        unsigned long long colOR = s_colOR;
        unsigned long long rowmask = (n == 64) ? ~0ull : ((1ull << n) - 1ull);
        if (colOR == 0ull) {
            unsigned long long keep = (~cross) & rowmask;
            int budget = NPOST - kcount;
            if (t < 64 && ((keep >> t) & 1ull)) {
                int rank = __popcll(keep & ((1ull << t) - 1ull));
                if (rank < budget) {
                    s_kept[kcount + rank] = base + t;
                    atomicOr(&s_alivew, 1ull << t);
                }
            }
            if (t == 0) {
                int pc = __popcll(keep);
                s_kc = kcount + (pc < budget ? pc : budget);
            }
        } else if (t == 0) {
            unsigned long long avail = (~cross) & rowmask;
            unsigned long long alivew = 0ull;
            int kc = kcount;
            while (avail && kc < NPOST) {
                int k1 = __ffsll((long long)avail) - 1;
                unsigned long long r = avail & (avail - 1);
                unsigned long long c1 = s_col[k1];
                int k2 = -1, k3 = -1, k4 = -1;
                unsigned long long c2 = 0, c3 = 0, c4 = 0;
                if (r) { k2 = __ffsll((long long)r) - 1; c2 = s_col[k2]; r &= r - 1;
                    if (r) { k3 = __ffsll((long long)r) - 1; c3 = s_col[k3]; r &= r - 1;
                        if (r) { k4 = __ffsll((long long)r) - 1; c4 = s_col[k4]; r &= r - 1; } } }
                unsigned long long m = c1;
                s_kept[kc++] = base + k1; alivew |= 1ull << k1;
                if (k2 >= 0 && kc < NPOST && !((m >> k2) & 1ull)) { s_kept[kc++] = base + k2; alivew |= 1ull << k2; m |= c2; }
                if (k3 >= 0 && kc < NPOST && !((m >> k3) & 1ull)) { s_kept[kc++] = base + k3; alivew |= 1ull << k3; m |= c3; }
                if (k4 >= 0 && kc < NPOST && !((m >> k4) & 1ull)) { s_kept[kc++] = base + k4; alivew |= 1ull << k4; m |= c4; }
                avail = r & ~m;
            }
            s_kc = kc; s_alivew = alivew;
        }
        __syncthreads();
        // Phase C: bookkeeping
        kcount = s_kc;
        if (t == 0) { s_alive[g] = s_alivew; s_cross = 0ull; s_colOR = 0ull; s_alivew = 0ull; }
        __syncthreads();
        if (kcount >= NPOST) break;
    }

    bool finished = (kcount >= NPOST) || (g1 >= NB);
    if (finished) {
        // write output straight from shared kept list
        for (int o = t; o < NPOST; o += 256) {
            if (o < kcount) {
                int i = s_kept[o];
                ((float4*)out)[o] = make_float4(g_y1[i], g_x1[i], g_y2[i], g_x2[i]);
                out[NPOST * 4 + o] = g_scores[i];
            } else {
                ((float4*)out)[o] = make_float4(0.f, 0.f, 0.f, 0.f);
                out[NPOST * 4 + o] = 0.f;
            }
        }
        __syncthreads();
        if (t == 0) { __threadfence(); g_done = 1; }
    } else {
        int kc0 = g_kcount;
        for (int i = kc0 + t; i < kcount; i += 256) g_kept[i] = s_kept[i];
        for (int i = t; i < NB; i += 256) g_alive[i] = s_alive[i];
        if (t == 0) g_kcount = kcount;
    }
}

// ---------------- K3/K4: fused mask + (last block) NMS ----------------------
// iou > 0.7  <=>  1.7*inter > 0.7*areaA + 0.7*areaB
__global__ void masknms_k(int col0, int total, int g0, int g1,
                          float* __restrict__ out, int phase) {
    int done = *(volatile int*)&g_done;
    int bx = col0 + blockIdx.x;
    int by = blockIdx.y;
    int t = threadIdx.x;                      // 256 threads
    __shared__ float4 colb[64];
    __shared__ float  colp[64];
    __shared__ int s_last;

    int rowlim = (bx + 1) * 64;               // rows needed for this column
    if (!done && by * 256 < rowlim) {
        if (t < 64) {
            int j = bx * 64 + t;
            colb[t] = make_float4(g_y1[j], g_x1[j], g_y2[j], g_x2[j]);
            colp[t] = g_pa[j];
        }
        __syncthreads();
        int i = by * 256 + t;
        if (i < rowlim) {
            float y1 = g_y1[i], x1 = g_x1[i], y2 = g_y2[i], x2 = g_x2[i];
            float pa = g_pa[i];
            unsigned long long m = 0ull;
            int c0 = i - bx * 64 + 1;         // >0 only on the diagonal group
            if (c0 <= 0) {
#pragma unroll 16
                for (int c = 0; c < 64; c++) {
                    float4 cb = colb[c];
                    float iy1 = fmaxf(y1, cb.x), ix1 = fmaxf(x1, cb.y);
                    float iy2 = fminf(y2, cb.z), ix2 = fminf(x2, cb.w);
                    float dy = fmaxf(iy2 - iy1, 0.f), dx = fmaxf(ix2 - ix1, 0.f);
                    bool cond = fmaf(1.7f, dy * dx, -pa) > colp[c];
                    m |= ((unsigned long long)cond) << c;
                }
            } else {
                for (int c = c0; c < 64; c++) {
                    float4 cb = colb[c];
                    float iy1 = fmaxf(y1, cb.x), ix1 = fmaxf(x1, cb.y);
                    float iy2 = fminf(y2, cb.z), ix2 = fminf(x2, cb.w);
                    float dy = fmaxf(iy2 - iy1, 0.f), dx = fmaxf(ix2 - ix1, 0.f);
                    bool cond = fmaf(1.7f, dy * dx, -pa) > colp[c];
                    m |= ((unsigned long long)cond) << c;
                }
            }
            g_maskT[bx][i] = m;
        }
    }
    // arrival: every block (incl. filtered/early-exit) counts exactly once
    __threadfence();
    __syncthreads();
    if (t == 0) {
        int* ctr = phase ? &g_mcount1 : &g_mcount0;
        s_last = (atomicAdd(ctr, 1) == total - 1);
    }
    __syncthreads();
    if (!s_last) return;

    // last block: run NMS over this chunk's groups (unless already done)
    if (!done) nms_run(g0, g1, out);

    if (phase) {
        // reset state for the next graph replay (runs after everything)
        __syncthreads();
        bool ok = (g_nstash >= NPRE && g_nstash <= STASH_CAP);
        for (int i = t; i < NB; i += 256) g_alive[i] = 0ull;
        if (!ok) for (int i = t; i < HB; i += 256) g_hist[i] = 0u;
        __syncthreads();
        if (t == 0) {
            g_kcount = 0; g_done = 0; g_nstash = 0;
            g_mcount0 = 0; g_mcount1 = 0;
        }
    }
}

// ---------------- launch ----------------------------------------------------
extern "C" void kernel_launch(void* const* d_in, const int* in_sizes, int n_in,
                              void* d_out, int out_size) {
    const float* enc    = (const float*)d_in[0];  // encoded_bboxes [N,4]
    const float* anch   = (const float*)d_in[1];  // anchors        [N,4]
    const float* scores = (const float*)d_in[2];  // scores         [N]
    float* out = (float*)d_out;                   // 2000*4 boxes + 2000 scores
    int n = in_sizes[2];
    int n4 = n / 4;

    scan_stash_k<<<1024, 256>>>((const float4*)scores, n4);
    sortdecode_k<<<256, 256>>>(enc, anch, scores, n);

    // chunk 1: columns/groups [0, G1); last mask block runs NMS
    {
        dim3 grid(G1, (G1 * 64 + 255) / 256);           // (48, 12)
        masknms_k<<<grid, 256>>>(0, grid.x * grid.y, 0, G1, out, 0);
    }
    // chunk 2: columns/groups [G1, NB); usually early-exits; resets state
    {
        dim3 grid(NB - G1, (NB * 64 + 255) / 256);      // (46, 24)
        masknms_k<<<grid, 256>>>(G1, grid.x * grid.y, G1, NB, out, 1);
    }
}

// round 13
// speedup vs baseline: 1.3666x; 1.3666x over previous
#include <cuda_runtime.h>
#include <stdint.h>

// Problem constants (fixed by the reference).
#define NPRE     6000
#define NPOST    2000
#define NB       94          // ceil(NPRE/64)
#define NROWS    (NB * 64)   // 6016, padded
#define HB       32768       // score histogram buckets (scores in [0,1))
#define BCAP     256         // per-bucket sort capacity
#define SCUT     (HB - 256)  // stash cut bucket
#define STASH_CAP 32768
#define SLOCAL   256         // per-block stash buffer
#define G1       48          // chunk boundary (groups, multiple of 4)
#define DCAP     1024        // dead-row list capacity

// ---------------- persistent device scratch (static zero-init at load) ------
__device__ unsigned           g_hist[HB];   // fallback path only
__device__ unsigned           g_base[HB];   // fallback path only
__device__ int                g_thresh;     // fallback path only
__device__ int                g_nstash;
__device__ int                g_scount;     // scan block counter (self-reset)
__device__ int                g_mcount0;    // masknms phase-0 counter
__device__ int                g_mcount1;    // masknms phase-1 counter
__device__ unsigned long long g_stash[STASH_CAP];
// SoA boxes (padded rows >= NPRE are never written -> stay zero)
__device__ float              g_y1[NROWS], g_x1[NROWS], g_y2[NROWS], g_x2[NROWS];
__device__ float              g_pa[NROWS];      // 0.7f * area
__device__ float              g_scores[NROWS];
__device__ unsigned long long g_maskT[NB][NROWS];   // [col_group][row]
__device__ unsigned long long g_colORall[NB];  // OR of col words, rows < supergroup base
__device__ unsigned long long g_alive[NB];
__device__ int                g_dead[DCAP];
__device__ int                g_ndead;
__device__ int                g_ndovf;
__device__ int                g_kept[NPOST];
__device__ int                g_kcount;
__device__ int                g_done;

__device__ __forceinline__ int score_bucket(float s) {
    int b = (int)(s * 32768.0f);
    return max(0, min(HB - 1, b));
}

// ---------------- K1: scan + stash + (last block) threshold check -----------
__global__ void scan_stash_k(const float4* __restrict__ s4, int n4) {
    __shared__ unsigned long long s_stash[SLOCAL];
    __shared__ int s_scnt, s_sbase, s_last;
    __shared__ unsigned sscan[256];
    int t = threadIdx.x;                      // 256 threads
    if (t == 0) s_scnt = 0;
    __syncthreads();
    int i = blockIdx.x * blockDim.x + t;
    int stride = gridDim.x * blockDim.x;
    for (; i < n4; i += stride) {
        float4 v = s4[i];
        float e[4] = {v.x, v.y, v.z, v.w};
#pragma unroll
        for (int c = 0; c < 4; c++) {
            if (score_bucket(e[c]) >= SCUT) {
                unsigned idx = (unsigned)(4 * i + c);
                unsigned long long key =
                    ((unsigned long long)__float_as_uint(e[c]) << 32)
                  | (unsigned long long)(0xFFFFFFFFu - idx);
                int p = atomicAdd(&s_scnt, 1);
                if (p < SLOCAL) s_stash[p] = key;
                else {                        // rare overflow: direct global
                    int q = atomicAdd(&g_nstash, 1);
                    if (q < STASH_CAP) g_stash[q] = key;
                }
            }
        }
    }
    __syncthreads();
    int cnt = s_scnt; if (cnt > SLOCAL) cnt = SLOCAL;
    if (t == 0) s_sbase = (cnt > 0) ? atomicAdd(&g_nstash, cnt) : 0;
    __syncthreads();
    for (int k = t; k < cnt; k += 256) {
        int q = s_sbase + k;
        if (q < STASH_CAP) g_stash[q] = s_stash[k];
    }
    // ---- last-block-done: threshold check (+exact fallback, never taken) ---
    __threadfence();
    __syncthreads();
    if (t == 0) s_last = (atomicAdd(&g_scount, 1) == (int)gridDim.x - 1);
    __syncthreads();
    if (!s_last) return;
    if (t == 0) g_scount = 0;                 // self-reset for next replay
    int ns = atomicAdd(&g_nstash, 0);
    if (ns >= NPRE && ns <= STASH_CAP) return;  // fast path: nothing to do
    // fallback: full histogram + descending rank bases (256 threads)
    for (int k = t; k < n4; k += 256) {
        float4 v = s4[k];
        atomicAdd(&g_hist[score_bucket(v.x)], 1u);
        atomicAdd(&g_hist[score_bucket(v.y)], 1u);
        atomicAdd(&g_hist[score_bucket(v.z)], 1u);
        atomicAdd(&g_hist[score_bucket(v.w)], 1u);
    }
    __syncthreads();
    int lo = HB - (t + 1) * 128;              // t owns buckets [lo, lo+128)
    unsigned sum = 0;
    for (int b = 0; b < 128; b++) sum += g_hist[lo + b];
    sscan[t] = sum;
    __syncthreads();
    for (int off = 1; off < 256; off <<= 1) {
        unsigned v = (t >= off) ? sscan[t - off] : 0u;
        __syncthreads();
        sscan[t] += v;
        __syncthreads();
    }
    unsigned run = sscan[t] - sum;            // count strictly above this chunk
    for (int b = 127; b >= 0; --b) {
        unsigned c = g_hist[lo + b];
        g_base[lo + b] = run;
        if (run < (unsigned)NPRE && run + c >= (unsigned)NPRE) g_thresh = lo + b;
        run += c;
    }
    if (t == 255 && sscan[255] < (unsigned)NPRE) g_thresh = 0;
}

// ---------------- K2: per-bucket gather + sort + decode (fused) -------------
__global__ void sortdecode_k(const float* __restrict__ enc,
                             const float* __restrict__ anch,
                             const float* __restrict__ scores, int n) {
    __shared__ unsigned long long s[BCAP];
    __shared__ int s_cnt, s_above;
    int t = threadIdx.x;                      // 256 threads
    int ns = g_nstash;
    bool ok = (ns >= NPRE && ns <= STASH_CAP);

    if (ok) {
        int b = HB - 1 - blockIdx.x;          // gridDim.x == 256
        if (t == 0) { s_cnt = 0; s_above = 0; }
        __syncthreads();
        int above = 0;
        for (int i = t; i < ns; i += 256) {
            unsigned long long key = g_stash[i];
            int kb = score_bucket(__uint_as_float((unsigned)(key >> 32)));
            if (kb > b) above++;
            else if (kb == b) {
                int p = atomicAdd(&s_cnt, 1);
                if (p < BCAP) s[p] = key;
            }
        }
        if (above) atomicAdd(&s_above, above);
        __syncthreads();
        int base = s_above;
        int cnt = s_cnt; if (cnt > BCAP) cnt = BCAP;
        if (base >= NPRE || cnt == 0) return;
        int kmax = 1; while (kmax < cnt) kmax <<= 1;
        for (int i = t; i < kmax; i += 256) if (i >= cnt) s[i] = 0ull;
        __syncthreads();
        for (int k = 2; k <= kmax; k <<= 1) {
            for (int j = k >> 1; j > 0; j >>= 1) {
                for (int p = t; p < (kmax >> 1); p += 256) {
                    int i = ((p & ~(j - 1)) << 1) | (p & (j - 1));
                    int x = i | j;
                    unsigned long long a = s[i], bb = s[x];
                    bool desc = ((i & k) == 0);
                    if (desc ? (a < bb) : (a > bb)) { s[i] = bb; s[x] = a; }
                }
                __syncthreads();
            }
        }
        int lim = cnt;
        if (base + lim > NPRE) lim = NPRE - base;
        for (int i = t; i < lim; i += 256) {
            unsigned long long key = s[i];
            int r = base + i;
            float y1 = 0.f, x1 = 0.f, y2 = 0.f, x2 = 0.f, sc = 0.f;
            unsigned idx = 0xFFFFFFFFu - (unsigned)(key & 0xFFFFFFFFull);
            if (idx < (unsigned)n) {
                sc = __uint_as_float((unsigned)(key >> 32));
                float4 a = ((const float4*)anch)[idx];   // [y1, x1, y2, x2]
                float4 e = ((const float4*)enc)[idx];    // [ty, tx, th, tw]
                float ha = a.z - a.x, wa = a.w - a.y;
                float cya = a.x + 0.5f * ha, cxa = a.y + 0.5f * wa;
                float cy = e.x * ha + cya;
                float cx = e.y * wa + cxa;
                float h  = expf(e.z) * ha;
                float w  = expf(e.w) * wa;
                y1 = cy - 0.5f * h; x1 = cx - 0.5f * w;
                y2 = cy + 0.5f * h; x2 = cx + 0.5f * w;
            }
            g_y1[r] = y1; g_x1[r] = x1; g_y2[r] = y2; g_x2[r] = x2;
            g_pa[r] = 0.7f * (y2 - y1) * (x2 - x1);
            g_scores[r] = sc;
        }
        return;
    }

    // ---- exact fallback (never taken for this data) -------------------------
    int T = g_thresh;
    for (int b = T + (int)blockIdx.x; b < HB; b += gridDim.x) {
        unsigned base = g_base[b];
        if (base >= (unsigned)NPRE) continue;
        if (t == 0) s_cnt = 0;
        __syncthreads();
        for (int i = t; i < n; i += 256) {
            float sv = scores[i];
            if (score_bucket(sv) == b) {
                int p = atomicAdd(&s_cnt, 1);
                if (p < BCAP)
                    s[p] = ((unsigned long long)__float_as_uint(sv) << 32)
                         | (unsigned long long)(0xFFFFFFFFu - (unsigned)i);
            }
        }
        __syncthreads();
        int cnt = s_cnt; if (cnt > BCAP) cnt = BCAP;
        if (cnt == 0) { __syncthreads(); continue; }
        int kmax = 1; while (kmax < cnt) kmax <<= 1;
        for (int i = t; i < kmax; i += 256) if (i >= cnt) s[i] = 0ull;
        __syncthreads();
        for (int k = 2; k <= kmax; k <<= 1) {
            for (int j = k >> 1; j > 0; j >>= 1) {
                for (int p = t; p < (kmax >> 1); p += 256) {
                    int i = ((p & ~(j - 1)) << 1) | (p & (j - 1));
                    int x = i | j;
                    unsigned long long a = s[i], bb = s[x];
                    bool desc = ((i & k) == 0);
                    if (desc ? (a < bb) : (a > bb)) { s[i] = bb; s[x] = a; }
                }
                __syncthreads();
            }
        }
        int lim = cnt;
        if ((int)base + lim > NPRE) lim = NPRE - (int)base;
        for (int i = t; i < lim; i += 256) {
            unsigned long long key = s[i];
            int r = (int)base + i;
            float y1 = 0.f, x1 = 0.f, y2 = 0.f, x2 = 0.f, sc = 0.f;
            unsigned idx = 0xFFFFFFFFu - (unsigned)(key & 0xFFFFFFFFull);
            if (idx < (unsigned)n) {
                sc = __uint_as_float((unsigned)(key >> 32));
                float4 a = ((const float4*)anch)[idx];
                float4 e = ((const float4*)enc)[idx];
                float ha = a.z - a.x, wa = a.w - a.y;
                float cya = a.x + 0.5f * ha, cxa = a.y + 0.5f * wa;
                float cy = e.x * ha + cya;
                float cx = e.y * wa + cxa;
                float h  = expf(e.z) * ha;
                float w  = expf(e.w) * wa;
                y1 = cy - 0.5f * h; x1 = cx - 0.5f * w;
                y2 = cy + 0.5f * h; x2 = cx + 0.5f * w;
            }
            g_y1[r] = y1; g_x1[r] = x1; g_y2[r] = y2; g_x2[r] = x2;
            g_pa[r] = 0.7f * (y2 - y1) * (x2 - x1);
            g_scores[r] = sc;
        }
        __syncthreads();
    }
}

// ---------------- NMS over supergroups of 4 column-groups -------------------
__device__ void nms_run(int g0, int g1, float* __restrict__ out) {
    __shared__ int                s_kept[NPOST];
    __shared__ int                s_dead[DCAP];
    __shared__ unsigned long long s_alive[NB];
    __shared__ unsigned long long s_blk[4][256];
    __shared__ unsigned long long s_cross[4], s_X[4], s_Y[4], s_aliveW[4];
    __shared__ unsigned long long s_inOR, s_ceff, s_dOR;
    __shared__ int s_kc, s_nd, s_ovf;
    int t = threadIdx.x;                       // 256 threads
    int kcount = g_kcount;
    int kc0 = kcount;
    for (int i = t; i < kcount; i += 256) s_kept[i] = g_kept[i];
    for (int i = t; i < NB; i += 256) s_alive[i] = g_alive[i];
    int nd0 = g_ndead;
    for (int i = t; i < nd0 && i < DCAP; i += 256) s_dead[i] = g_dead[i];
    if (t == 0) { s_nd = nd0; s_ovf = g_ndovf; s_kc = kcount; }
    __syncthreads();

    if (g1 > NB) g1 = NB;
    for (int G = g0; G < g1; G += 4) {
        int w = g1 - G; if (w > 4) w = 4;
        int base = G * 64;
        if (t < 4) { s_cross[t] = 0ull; s_Y[t] = 0ull; s_X[t] = 0ull; s_aliveW[t] = 0ull; }
        if (t == 0) s_inOR = 0ull;
        __syncthreads();
        int c = t >> 6, lane = t & 63;
        // A1: in-block words (upper-triangular region only; rest zero)
        {
            unsigned long long acc = 0ull;
#pragma unroll
            for (int k = 0; k < 4; k++) {
                int rp = lane + k * 64;
                unsigned long long wv = 0ull;
                if (c < w && rp < 64 * (c + 1)) wv = g_maskT[G + c][base + rp];
                s_blk[c][rp] = wv;
                acc |= wv;
            }
            if (acc) atomicOr(&s_inOR, acc);
        }
        // A2: dead contributions Y + prefetch X = colORall
        if (c < w) {
            if (lane == 0) s_X[c] = g_colORall[G + c];
            unsigned long long p = 0ull;
            int nd = s_nd; if (nd > DCAP) nd = DCAP;
            for (int i = lane; i < nd; i += 64) p |= g_maskT[G + c][s_dead[i]];
            if (p) atomicOr(&s_Y[c], p);
        }
        __syncthreads();
        bool ovf = (s_ovf != 0) || (s_nd > DCAP);
        if (t < 4) s_cross[t] = ((s_Y[t] == 0ull) && !ovf) ? s_X[t] : 0ull;
        __syncthreads();
        // rare: exact full scan for columns with dead contributions
        for (int cc = 0; cc < w; cc++) {
            if ((s_Y[cc] != 0ull) || ovf) {
                const unsigned long long* colp_ = g_maskT[G + cc];
                unsigned long long p = 0ull;
                for (int r = t; r < base; r += 256)
                    p |= colp_[r] & (0ull - ((s_alive[r >> 6] >> (r & 63)) & 1ull));
                if (p) atomicOr(&s_cross[cc], p);
            }
        }
        __syncthreads();
        // B: decision
        int budget = NPOST - kcount;
        if (s_inOR == 0ull) {
            // no suppression within this superstep: fully parallel emit
            unsigned long long kp[4]; int pc[4];
#pragma unroll
            for (int cc = 0; cc < 4; cc++) {
                int nn = NPRE - (base + cc * 64);
                nn = nn < 0 ? 0 : (nn > 64 ? 64 : nn);
                unsigned long long rm = (nn == 64) ? ~0ull
                                       : ((nn == 0) ? 0ull : ((1ull << nn) - 1ull));
                kp[cc] = (cc < w) ? ((~s_cross[cc]) & rm) : 0ull;
                pc[cc] = __popcll(kp[cc]);
            }
            if (c < w && ((kp[c] >> lane) & 1ull)) {
                int off = 0;
                for (int cc = 0; cc < c; cc++) off += pc[cc];
                int rank = off + __popcll(kp[c] & ((1ull << lane) - 1ull));
                if (rank < budget) {
                    s_kept[kcount + rank] = base + c * 64 + lane;
                    atomicOr(&s_aliveW[c], 1ull << lane);
                }
            }
            if (t == 0) {
                int tot = pc[0] + pc[1] + pc[2] + pc[3];
                s_kc = kcount + (tot < budget ? tot : budget);
            }
            __syncthreads();
            kcount = s_kc;
        } else {
            // rare: resolve sub-groups sequentially
            for (int cc = 0; cc < w; cc++) {
                if (t == 0) { s_ceff = s_cross[cc]; s_dOR = 0ull; }
                __syncthreads();
                {
                    unsigned long long p = 0ull;
                    for (int rp = t; rp < 64 * cc; rp += 256)
                        p |= s_blk[cc][rp] & (0ull - ((s_aliveW[rp >> 6] >> (rp & 63)) & 1ull));
                    if (p) atomicOr(&s_ceff, p);
                }
                if (t < 64) {
                    unsigned long long wv = s_blk[cc][64 * cc + t];
                    if (wv) atomicOr(&s_dOR, wv);
                }
                __syncthreads();
                int nn = NPRE - (base + cc * 64);
                nn = nn < 0 ? 0 : (nn > 64 ? 64 : nn);
                unsigned long long rm = (nn == 64) ? ~0ull
                                       : ((nn == 0) ? 0ull : ((1ull << nn) - 1ull));
                unsigned long long cross = s_ceff;
                int bud = NPOST - kcount;
                if (s_dOR == 0ull) {
                    unsigned long long keep = (~cross) & rm;
                    if (t < 64 && ((keep >> t) & 1ull)) {
                        int rank = __popcll(keep & ((1ull << t) - 1ull));
                        if (rank < bud) {
                            s_kept[kcount + rank] = base + cc * 64 + t;
                            atomicOr(&s_aliveW[cc], 1ull << t);
                        }
                    }
                    if (t == 0) {
                        int pcn = __popcll(keep);
                        s_kc = kcount + (pcn < bud ? pcn : bud);
                    }
                } else if (t == 0) {
                    unsigned long long avail = (~cross) & rm;
                    unsigned long long alivew = 0ull;
                    int kc = kcount;
                    while (avail && kc < NPOST) {
                        int k1 = __ffsll((long long)avail) - 1;
                        avail &= avail - 1;
                        unsigned long long c1 = s_blk[cc][64 * cc + k1];
                        s_kept[kc++] = base + cc * 64 + k1;
                        alivew |= 1ull << k1;
                        avail &= ~c1;
                    }
                    s_kc = kc;
                    s_aliveW[cc] = alivew;
                }
                __syncthreads();
                kcount = s_kc;
                if (kcount >= NPOST) break;
            }
        }
        // C: commit alive + append dead rows
        if (t < 4 && t < w) s_alive[G + t] = s_aliveW[t];
        bool fin = (kcount >= NPOST);
        if (!fin && c < w) {
            int row = base + 64 * c + lane;
            if (row < NPRE && !((s_aliveW[c] >> lane) & 1ull)) {
                int p = atomicAdd(&s_nd, 1);
                if (p < DCAP) s_dead[p] = row;
                else s_ovf = 1;
            }
        }
        __syncthreads();
        if (fin) break;
    }

    bool finished = (kcount >= NPOST) || (g1 >= NB);
    if (finished) {
        for (int o = t; o < NPOST; o += 256) {
            if (o < kcount) {
                int i = s_kept[o];
                ((float4*)out)[o] = make_float4(g_y1[i], g_x1[i], g_y2[i], g_x2[i]);
                out[NPOST * 4 + o] = g_scores[i];
            } else {
                ((float4*)out)[o] = make_float4(0.f, 0.f, 0.f, 0.f);
                out[NPOST * 4 + o] = 0.f;
            }
        }
        __syncthreads();
        if (t == 0) { __threadfence(); g_done = 1; }
    } else {
        for (int i = kc0 + t; i < kcount; i += 256) g_kept[i] = s_kept[i];
        for (int i = t; i < NB; i += 256) g_alive[i] = s_alive[i];
        int nd = s_nd; if (nd > DCAP) nd = DCAP;
        for (int i = nd0 + t; i < nd; i += 256) g_dead[i] = s_dead[i];
        if (t == 0) { g_kcount = kcount; g_ndead = s_nd; g_ndovf = s_ovf; }
    }
}

// ---------------- K3/K4: fused mask + colORall + (last block) NMS -----------
// iou > 0.7  <=>  1.7*inter > 0.7*areaA + 0.7*areaB
__global__ void masknms_k(int col0, int total, int g0, int g1,
                          float* __restrict__ out, int phase) {
    int done = *(volatile int*)&g_done;
    int bx = col0 + blockIdx.x;
    int by = blockIdx.y;
    int t = threadIdx.x;                      // 256 threads
    __shared__ float4 colb[64];
    __shared__ float  colp[64];
    __shared__ unsigned long long s_or;
    __shared__ int s_last;

    int rowlim = (bx + 1) * 64;               // rows needed for this column
    if (!done && by * 256 < rowlim) {
        if (t == 0) s_or = 0ull;
        if (t < 64) {
            int j = bx * 64 + t;
            colb[t] = make_float4(g_y1[j], g_x1[j], g_y2[j], g_x2[j]);
            colp[t] = g_pa[j];
        }
        __syncthreads();
        int i = by * 256 + t;
        int basesup = (bx & ~3) * 64;         // supergroup base of this column
        if (i < rowlim) {
            float y1 = g_y1[i], x1 = g_x1[i], y2 = g_y2[i], x2 = g_x2[i];
            float pa = g_pa[i];
            unsigned long long m = 0ull;
            int c0 = i - bx * 64 + 1;         // >0 only on the diagonal group
            if (c0 <= 0) {
#pragma unroll 16
                for (int c = 0; c < 64; c++) {
                    float4 cb = colb[c];
                    float iy1 = fmaxf(y1, cb.x), ix1 = fmaxf(x1, cb.y);
                    float iy2 = fminf(y2, cb.z), ix2 = fminf(x2, cb.w);
                    float dy = fmaxf(iy2 - iy1, 0.f), dx = fmaxf(ix2 - ix1, 0.f);
                    bool cond = fmaf(1.7f, dy * dx, -pa) > colp[c];
                    m |= ((unsigned long long)cond) << c;
                }
            } else {
                for (int c = c0; c < 64; c++) {
                    float4 cb = colb[c];
                    float iy1 = fmaxf(y1, cb.x), ix1 = fmaxf(x1, cb.y);
                    float iy2 = fminf(y2, cb.z), ix2 = fminf(x2, cb.w);
                    float dy = fmaxf(iy2 - iy1, 0.f), dx = fmaxf(ix2 - ix1, 0.f);
                    bool cond = fmaf(1.7f, dy * dx, -pa) > colp[c];
                    m |= ((unsigned long long)cond) << c;
                }
            }
            g_maskT[bx][i] = m;
            if (m && i < basesup) atomicOr(&s_or, m);   // contribution to colORall
        }
        __syncthreads();
        if (t == 0 && s_or) atomicOr(&g_colORall[bx], s_or);
    }
    // arrival: every block (incl. filtered/early-exit) counts exactly once
    __threadfence();
    __syncthreads();
    if (t == 0) {
        int* ctr = phase ? &g_mcount1 : &g_mcount0;
        s_last = (atomicAdd(ctr, 1) == total - 1);
    }
    __syncthreads();
    if (!s_last) return;

    // last block: run NMS over this chunk's groups (unless already done)
    if (!done) nms_run(g0, g1, out);

    if (phase) {
        // reset state for the next graph replay (runs after everything)
        __syncthreads();
        bool ok = (g_nstash >= NPRE && g_nstash <= STASH_CAP);
        for (int i = t; i < NB; i += 256) { g_alive[i] = 0ull; g_colORall[i] = 0ull; }
        if (!ok) for (int i = t; i < HB; i += 256) g_hist[i] = 0u;
        __syncthreads();
        if (t == 0) {
            g_kcount = 0; g_done = 0; g_nstash = 0;
            g_mcount0 = 0; g_mcount1 = 0;
            g_ndead = 0; g_ndovf = 0;
        }
    }
}

// ---------------- launch ----------------------------------------------------
extern "C" void kernel_launch(void* const* d_in, const int* in_sizes, int n_in,
                              void* d_out, int out_size) {
    const float* enc    = (const float*)d_in[0];  // encoded_bboxes [N,4]
    const float* anch   = (const float*)d_in[1];  // anchors        [N,4]
    const float* scores = (const float*)d_in[2];  // scores         [N]
    float* out = (float*)d_out;                   // 2000*4 boxes + 2000 scores
    int n = in_sizes[2];
    int n4 = n / 4;

    scan_stash_k<<<1024, 256>>>((const float4*)scores, n4);
    sortdecode_k<<<256, 256>>>(enc, anch, scores, n);

    // chunk 1: columns/groups [0, G1); last mask block runs NMS
    {
        dim3 grid(G1, (G1 * 64 + 255) / 256);           // (48, 12)
        masknms_k<<<grid, 256>>>(0, grid.x * grid.y, 0, G1, out, 0);
    }
    // chunk 2: columns/groups [G1, NB); usually early-exits; resets state
    {
        dim3 grid(NB - G1, (NB * 64 + 255) / 256);      // (46, 24)
        masknms_k<<<grid, 256>>>(G1, grid.x * grid.y, G1, NB, out, 1);
    }
}

// round 14
// speedup vs baseline: 1.9302x; 1.4124x over previous
#include <cuda_runtime.h>
#include <stdint.h>

// Problem constants (fixed by the reference).
#define NPRE     6000
#define NPOST    2000
#define NB       94          // ceil(NPRE/64)
#define NROWS    (NB * 64)   // 6016, padded
#define HB       32768       // score histogram buckets (scores in [0,1))
#define BCAP     256         // per-bucket sort capacity
#define SCUT     (HB - 256)  // stash cut bucket
#define STASH_CAP 32768
#define SLOCAL   256         // per-block stash buffer
#define G1       44          // chunk boundary (groups, multiple of 4)
#define DCAP     1024        // dead-row list capacity

// ---------------- persistent device scratch (static zero-init at load) ------
__device__ unsigned           g_hist[HB];   // fallback path only
__device__ unsigned           g_base[HB];   // fallback path only
__device__ int                g_thresh;     // fallback path only
__device__ int                g_nstash;
__device__ int                g_scount;     // scan block counter (self-reset)
__device__ int                g_mcount0;    // masknms phase-0 counter
__device__ int                g_mcount1;    // masknms phase-1 counter
__device__ unsigned long long g_stash[STASH_CAP];
// SoA boxes (padded rows >= NPRE are never written -> stay zero)
__device__ float              g_y1[NROWS], g_x1[NROWS], g_y2[NROWS], g_x2[NROWS];
__device__ float              g_pa[NROWS];      // 0.7f * area
__device__ float              g_scores[NROWS];
__device__ unsigned long long g_maskT[NB][NROWS];   // [col_group][row]
__device__ unsigned long long g_colORall[NB];  // OR of col words, rows < supergroup base
__device__ unsigned long long g_alive[NB];
__device__ int                g_dead[DCAP];
__device__ int                g_ndead;
__device__ int                g_ndovf;
__device__ int                g_kept[NPOST];
__device__ int                g_kcount;
__device__ int                g_done;

__device__ __forceinline__ int score_bucket(float s) {
    int b = (int)(s * 32768.0f);
    return max(0, min(HB - 1, b));
}

// ---------------- K1: scan + stash + (last block) threshold check -----------
__global__ void scan_stash_k(const float4* __restrict__ s4, int n4) {
    __shared__ unsigned long long s_stash[SLOCAL];
    __shared__ int s_scnt, s_sbase, s_last;
    __shared__ unsigned sscan[256];
    int t = threadIdx.x;                      // 256 threads
    if (t == 0) s_scnt = 0;
    __syncthreads();
    int i = blockIdx.x * blockDim.x + t;
    int stride = gridDim.x * blockDim.x;
    for (; i < n4; i += stride) {
        float4 v = s4[i];
        float e[4] = {v.x, v.y, v.z, v.w};
#pragma unroll
        for (int c = 0; c < 4; c++) {
            if (score_bucket(e[c]) >= SCUT) {
                unsigned idx = (unsigned)(4 * i + c);
                unsigned long long key =
                    ((unsigned long long)__float_as_uint(e[c]) << 32)
                  | (unsigned long long)(0xFFFFFFFFu - idx);
                int p = atomicAdd(&s_scnt, 1);
                if (p < SLOCAL) s_stash[p] = key;
                else {                        // rare overflow: direct global
                    int q = atomicAdd(&g_nstash, 1);
                    if (q < STASH_CAP) g_stash[q] = key;
                }
            }
        }
    }
    __syncthreads();
    int cnt = s_scnt; if (cnt > SLOCAL) cnt = SLOCAL;
    if (t == 0) s_sbase = (cnt > 0) ? atomicAdd(&g_nstash, cnt) : 0;
    __syncthreads();
    for (int k = t; k < cnt; k += 256) {
        int q = s_sbase + k;
        if (q < STASH_CAP) g_stash[q] = s_stash[k];
    }
    // ---- last-block-done: threshold check (+exact fallback, never taken) ---
    __threadfence();
    __syncthreads();
    if (t == 0) s_last = (atomicAdd(&g_scount, 1) == (int)gridDim.x - 1);
    __syncthreads();
    if (!s_last) return;
    if (t == 0) g_scount = 0;                 // self-reset for next replay
    int ns = atomicAdd(&g_nstash, 0);
    if (ns >= NPRE && ns <= STASH_CAP) return;  // fast path: nothing to do
    // fallback: full histogram + descending rank bases (256 threads)
    for (int k = t; k < n4; k += 256) {
        float4 v = s4[k];
        atomicAdd(&g_hist[score_bucket(v.x)], 1u);
        atomicAdd(&g_hist[score_bucket(v.y)], 1u);
        atomicAdd(&g_hist[score_bucket(v.z)], 1u);
        atomicAdd(&g_hist[score_bucket(v.w)], 1u);
    }
    __syncthreads();
    int lo = HB - (t + 1) * 128;              // t owns buckets [lo, lo+128)
    unsigned sum = 0;
    for (int b = 0; b < 128; b++) sum += g_hist[lo + b];
    sscan[t] = sum;
    __syncthreads();
    for (int off = 1; off < 256; off <<= 1) {
        unsigned v = (t >= off) ? sscan[t - off] : 0u;
        __syncthreads();
        sscan[t] += v;
        __syncthreads();
    }
    unsigned run = sscan[t] - sum;            // count strictly above this chunk
    for (int b = 127; b >= 0; --b) {
        unsigned c = g_hist[lo + b];
        g_base[lo + b] = run;
        if (run < (unsigned)NPRE && run + c >= (unsigned)NPRE) g_thresh = lo + b;
        run += c;
    }
    if (t == 255 && sscan[255] < (unsigned)NPRE) g_thresh = 0;
}

// ---------------- K2: per-bucket gather + sort + decode (fused) -------------
__global__ void sortdecode_k(const float* __restrict__ enc,
                             const float* __restrict__ anch,
                             const float* __restrict__ scores, int n) {
    __shared__ unsigned long long s[BCAP];
    __shared__ int s_cnt, s_above;
    int t = threadIdx.x;                      // 256 threads
    int ns = g_nstash;
    bool ok = (ns >= NPRE && ns <= STASH_CAP);

    if (ok) {
        int b = HB - 1 - blockIdx.x;          // gridDim.x == 256
        if (t == 0) { s_cnt = 0; s_above = 0; }
        __syncthreads();
        int above = 0;
        for (int i = t; i < ns; i += 256) {
            unsigned long long key = g_stash[i];
            int kb = score_bucket(__uint_as_float((unsigned)(key >> 32)));
            if (kb > b) above++;
            else if (kb == b) {
                int p = atomicAdd(&s_cnt, 1);
                if (p < BCAP) s[p] = key;
            }
        }
        if (above) atomicAdd(&s_above, above);
        __syncthreads();
        int base = s_above;
        int cnt = s_cnt; if (cnt > BCAP) cnt = BCAP;
        if (base >= NPRE || cnt == 0) return;
        int kmax = 1; while (kmax < cnt) kmax <<= 1;
        for (int i = t; i < kmax; i += 256) if (i >= cnt) s[i] = 0ull;
        __syncthreads();
        for (int k = 2; k <= kmax; k <<= 1) {
            for (int j = k >> 1; j > 0; j >>= 1) {
                for (int p = t; p < (kmax >> 1); p += 256) {
                    int i = ((p & ~(j - 1)) << 1) | (p & (j - 1));
                    int x = i | j;
                    unsigned long long a = s[i], bb = s[x];
                    bool desc = ((i & k) == 0);
                    if (desc ? (a < bb) : (a > bb)) { s[i] = bb; s[x] = a; }
                }
                __syncthreads();
            }
        }
        int lim = cnt;
        if (base + lim > NPRE) lim = NPRE - base;
        for (int i = t; i < lim; i += 256) {
            unsigned long long key = s[i];
            int r = base + i;
            float y1 = 0.f, x1 = 0.f, y2 = 0.f, x2 = 0.f, sc = 0.f;
            unsigned idx = 0xFFFFFFFFu - (unsigned)(key & 0xFFFFFFFFull);
            if (idx < (unsigned)n) {
                sc = __uint_as_float((unsigned)(key >> 32));
                float4 a = ((const float4*)anch)[idx];   // [y1, x1, y2, x2]
                float4 e = ((const float4*)enc)[idx];    // [ty, tx, th, tw]
                float ha = a.z - a.x, wa = a.w - a.y;
                float cya = a.x + 0.5f * ha, cxa = a.y + 0.5f * wa;
                float cy = e.x * ha + cya;
                float cx = e.y * wa + cxa;
                float h  = expf(e.z) * ha;
                float w  = expf(e.w) * wa;
                y1 = cy - 0.5f * h; x1 = cx - 0.5f * w;
                y2 = cy + 0.5f * h; x2 = cx + 0.5f * w;
            }
            g_y1[r] = y1; g_x1[r] = x1; g_y2[r] = y2; g_x2[r] = x2;
            g_pa[r] = 0.7f * (y2 - y1) * (x2 - x1);
            g_scores[r] = sc;
        }
        return;
    }

    // ---- exact fallback (never taken for this data) -------------------------
    int T = g_thresh;
    for (int b = T + (int)blockIdx.x; b < HB; b += gridDim.x) {
        unsigned base = g_base[b];
        if (base >= (unsigned)NPRE) continue;
        if (t == 0) s_cnt = 0;
        __syncthreads();
        for (int i = t; i < n; i += 256) {
            float sv = scores[i];
            if (score_bucket(sv) == b) {
                int p = atomicAdd(&s_cnt, 1);
                if (p < BCAP)
                    s[p] = ((unsigned long long)__float_as_uint(sv) << 32)
                         | (unsigned long long)(0xFFFFFFFFu - (unsigned)i);
            }
        }
        __syncthreads();
        int cnt = s_cnt; if (cnt > BCAP) cnt = BCAP;
        if (cnt == 0) { __syncthreads(); continue; }
        int kmax = 1; while (kmax < cnt) kmax <<= 1;
        for (int i = t; i < kmax; i += 256) if (i >= cnt) s[i] = 0ull;
        __syncthreads();
        for (int k = 2; k <= kmax; k <<= 1) {
            for (int j = k >> 1; j > 0; j >>= 1) {
                for (int p = t; p < (kmax >> 1); p += 256) {
                    int i = ((p & ~(j - 1)) << 1) | (p & (j - 1));
                    int x = i | j;
                    unsigned long long a = s[i], bb = s[x];
                    bool desc = ((i & k) == 0);
                    if (desc ? (a < bb) : (a > bb)) { s[i] = bb; s[x] = a; }
                }
                __syncthreads();
            }
        }
        int lim = cnt;
        if ((int)base + lim > NPRE) lim = NPRE - (int)base;
        for (int i = t; i < lim; i += 256) {
            unsigned long long key = s[i];
            int r = (int)base + i;
            float y1 = 0.f, x1 = 0.f, y2 = 0.f, x2 = 0.f, sc = 0.f;
            unsigned idx = 0xFFFFFFFFu - (unsigned)(key & 0xFFFFFFFFull);
            if (idx < (unsigned)n) {
                sc = __uint_as_float((unsigned)(key >> 32));
                float4 a = ((const float4*)anch)[idx];
                float4 e = ((const float4*)enc)[idx];
                float ha = a.z - a.x, wa = a.w - a.y;
                float cya = a.x + 0.5f * ha, cxa = a.y + 0.5f * wa;
                float cy = e.x * ha + cya;
                float cx = e.y * wa + cxa;
                float h  = expf(e.z) * ha;
                float w  = expf(e.w) * wa;
                y1 = cy - 0.5f * h; x1 = cx - 0.5f * w;
                y2 = cy + 0.5f * h; x2 = cx + 0.5f * w;
            }
            g_y1[r] = y1; g_x1[r] = x1; g_y2[r] = y2; g_x2[r] = x2;
            g_pa[r] = 0.7f * (y2 - y1) * (x2 - x1);
            g_scores[r] = sc;
        }
        __syncthreads();
    }
}

// ---------------- NMS over supergroups, sparse in-superstep resolution ------
__device__ void nms_run(int g0, int g1, float* __restrict__ out) {
    __shared__ int                s_kept[NPOST];
    __shared__ int                s_dead[DCAP];
    __shared__ unsigned long long s_alive[NB];
    __shared__ unsigned long long s_blk[4][256];
    __shared__ unsigned long long s_cross[4], s_X[4], s_Y[4], s_aliveW[4];
    __shared__ unsigned long long s_pres[4], s_keep[4];
    __shared__ int s_kc, s_nd, s_ovf;
    int t = threadIdx.x;                       // 256 threads
    int kcount = g_kcount;
    int kc0 = kcount;
    for (int i = t; i < kcount; i += 256) s_kept[i] = g_kept[i];
    for (int i = t; i < NB; i += 256) s_alive[i] = g_alive[i];
    int nd0 = g_ndead;
    for (int i = t; i < nd0 && i < DCAP; i += 256) s_dead[i] = g_dead[i];
    if (t == 0) { s_nd = nd0; s_ovf = g_ndovf; s_kc = kcount; }
    __syncthreads();

    if (g1 > NB) g1 = NB;
    for (int G = g0; G < g1; G += 4) {
        int w = g1 - G; if (w > 4) w = 4;
        int base = G * 64;
        if (t < 4) { s_cross[t] = 0ull; s_Y[t] = 0ull; s_X[t] = 0ull;
                     s_aliveW[t] = 0ull; s_pres[t] = 0ull; }
        __syncthreads();
        int c = t >> 6, lane = t & 63;
        // A1: in-block words (upper-triangular region only; rest zero)
#pragma unroll
        for (int k = 0; k < 4; k++) {
            int rp = lane + k * 64;
            unsigned long long wv = 0ull;
            if (c < w && rp < 64 * (c + 1)) wv = g_maskT[G + c][base + rp];
            s_blk[c][rp] = wv;
        }
        // A2: dead contributions Y + prefetch X = colORall
        if (c < w) {
            if (lane == 0) s_X[c] = g_colORall[G + c];
            unsigned long long p = 0ull;
            int nd = s_nd; if (nd > DCAP) nd = DCAP;
            for (int i = lane; i < nd; i += 64) p |= g_maskT[G + c][s_dead[i]];
            if (p) atomicOr(&s_Y[c], p);
        }
        __syncthreads();
        // presence bitmap of rows with any in-superstep suppression word
        {
            unsigned long long rowOR = s_blk[0][t] | s_blk[1][t]
                                     | s_blk[2][t] | s_blk[3][t];
            if (rowOR) atomicOr(&s_pres[t >> 6], 1ull << (t & 63));
        }
        bool ovf = (s_ovf != 0) || (s_nd > DCAP);
        if (t < 4) s_cross[t] = ((s_Y[t] == 0ull) && !ovf) ? s_X[t] : 0ull;
        __syncthreads();
        // rare: exact full scan for columns with dead contributions
        for (int cc = 0; cc < w; cc++) {
            if ((s_Y[cc] != 0ull) || ovf) {
                const unsigned long long* colp_ = g_maskT[G + cc];
                unsigned long long p = 0ull;
                for (int r = t; r < base; r += 256)
                    p |= colp_[r] & (0ull - ((s_alive[r >> 6] >> (r & 63)) & 1ull));
                if (p) atomicOr(&s_cross[cc], p);
            }
        }
        __syncthreads();
        // resolve: common case zero presence -> keep = ~cross; else thread 0
        // walks the (tiny) set of suppressor rows in ascending order.
        unsigned long long anynz = s_pres[0] | s_pres[1] | s_pres[2] | s_pres[3];
        if (anynz == 0ull) {
            if (t < 4) {
                int nn = NPRE - (base + t * 64);
                nn = nn < 0 ? 0 : (nn > 64 ? 64 : nn);
                unsigned long long rm = (nn == 64) ? ~0ull
                                       : ((nn == 0) ? 0ull : ((1ull << nn) - 1ull));
                s_keep[t] = (t < w) ? ((~s_cross[t]) & rm) : 0ull;
            }
        } else if (t == 0) {
            unsigned long long alive[4];
#pragma unroll
            for (int cc = 0; cc < 4; cc++) {
                int nn = NPRE - (base + cc * 64);
                nn = nn < 0 ? 0 : (nn > 64 ? 64 : nn);
                unsigned long long rm = (nn == 64) ? ~0ull
                                       : ((nn == 0) ? 0ull : ((1ull << nn) - 1ull));
                alive[cc] = (cc < w) ? ((~s_cross[cc]) & rm) : 0ull;
            }
#pragma unroll
            for (int w64 = 0; w64 < 4; w64++) {
                unsigned long long pres = s_pres[w64];
                while (pres) {
                    int b_ = __ffsll((long long)pres) - 1;
                    pres &= pres - 1;
                    int rp = w64 * 64 + b_;
                    if ((alive[rp >> 6] >> (rp & 63)) & 1ull) {
                        alive[0] &= ~s_blk[0][rp];
                        alive[1] &= ~s_blk[1][rp];
                        alive[2] &= ~s_blk[2][rp];
                        alive[3] &= ~s_blk[3][rp];
                    }
                }
            }
            s_keep[0] = alive[0]; s_keep[1] = alive[1];
            s_keep[2] = alive[2]; s_keep[3] = alive[3];
        }
        __syncthreads();
        // emit (common): rank-ordered parallel write
        int budget = NPOST - kcount;
        int pc0 = __popcll(s_keep[0]), pc1 = __popcll(s_keep[1]);
        int pc2 = __popcll(s_keep[2]), pc3 = __popcll(s_keep[3]);
        if ((s_keep[c] >> lane) & 1ull) {
            int off = (c > 0 ? pc0 : 0) + (c > 1 ? pc1 : 0) + (c > 2 ? pc2 : 0);
            int rank = off + __popcll(s_keep[c] & ((1ull << lane) - 1ull));
            if (rank < budget) {
                s_kept[kcount + rank] = base + t;
                atomicOr(&s_aliveW[c], 1ull << lane);
            }
        }
        if (t == 0) {
            int tot = pc0 + pc1 + pc2 + pc3;
            s_kc = kcount + (tot < budget ? tot : budget);
        }
        __syncthreads();
        kcount = s_kc;
        // C: commit alive + append dead rows
        if (t < 4 && t < w) s_alive[G + t] = s_aliveW[t];
        bool fin = (kcount >= NPOST);
        if (!fin && c < w) {
            int row = base + t;
            if (row < NPRE && !((s_aliveW[c] >> lane) & 1ull)) {
                int p = atomicAdd(&s_nd, 1);
                if (p < DCAP) s_dead[p] = row;
                else s_ovf = 1;
            }
        }
        __syncthreads();
        if (fin) break;
    }

    bool finished = (kcount >= NPOST) || (g1 >= NB);
    if (finished) {
        for (int o = t; o < NPOST; o += 256) {
            if (o < kcount) {
                int i = s_kept[o];
                ((float4*)out)[o] = make_float4(g_y1[i], g_x1[i], g_y2[i], g_x2[i]);
                out[NPOST * 4 + o] = g_scores[i];
            } else {
                ((float4*)out)[o] = make_float4(0.f, 0.f, 0.f, 0.f);
                out[NPOST * 4 + o] = 0.f;
            }
        }
        __syncthreads();
        if (t == 0) { __threadfence(); g_done = 1; }
    } else {
        for (int i = kc0 + t; i < kcount; i += 256) g_kept[i] = s_kept[i];
        for (int i = t; i < NB; i += 256) g_alive[i] = s_alive[i];
        int nd = s_nd; if (nd > DCAP) nd = DCAP;
        for (int i = nd0 + t; i < nd; i += 256) g_dead[i] = s_dead[i];
        if (t == 0) { g_kcount = kcount; g_ndead = s_nd; g_ndovf = s_ovf; }
    }
}

// ---------------- K3/K4: fused mask + colORall + (last block) NMS -----------
// iou > 0.7  <=>  1.7*inter > 0.7*areaA + 0.7*areaB
__global__ void masknms_k(int col0, int total, int g0, int g1,
                          float* __restrict__ out, int phase) {
    int done = *(volatile int*)&g_done;
    int bx = col0 + blockIdx.x;
    int by = blockIdx.y;
    int t = threadIdx.x;                      // 256 threads
    __shared__ float4 colb[64];
    __shared__ float  colp[64];
    __shared__ unsigned long long s_or;
    __shared__ int s_last;

    int rowlim = (bx + 1) * 64;               // rows needed for this column
    if (!done && by * 256 < rowlim) {
        if (t == 0) s_or = 0ull;
        if (t < 64) {
            int j = bx * 64 + t;
            colb[t] = make_float4(g_y1[j], g_x1[j], g_y2[j], g_x2[j]);
            colp[t] = g_pa[j];
        }
        __syncthreads();
        int i = by * 256 + t;
        int basesup = (bx & ~3) * 64;         // supergroup base of this column
        if (i < rowlim) {
            float y1 = g_y1[i], x1 = g_x1[i], y2 = g_y2[i], x2 = g_x2[i];
            float pa = g_pa[i];
            unsigned long long m = 0ull;
            int c0 = i - bx * 64 + 1;         // >0 only on the diagonal group
            if (c0 <= 0) {
#pragma unroll 16
                for (int c = 0; c < 64; c++) {
                    float4 cb = colb[c];
                    float iy1 = fmaxf(y1, cb.x), ix1 = fmaxf(x1, cb.y);
                    float iy2 = fminf(y2, cb.z), ix2 = fminf(x2, cb.w);
                    float dy = fmaxf(iy2 - iy1, 0.f), dx = fmaxf(ix2 - ix1, 0.f);
                    bool cond = fmaf(1.7f, dy * dx, -pa) > colp[c];
                    m |= ((unsigned long long)cond) << c;
                }
            } else {
                for (int c = c0; c < 64; c++) {
                    float4 cb = colb[c];
                    float iy1 = fmaxf(y1, cb.x), ix1 = fmaxf(x1, cb.y);
                    float iy2 = fminf(y2, cb.z), ix2 = fminf(x2, cb.w);
                    float dy = fmaxf(iy2 - iy1, 0.f), dx = fmaxf(ix2 - ix1, 0.f);
                    bool cond = fmaf(1.7f, dy * dx, -pa) > colp[c];
                    m |= ((unsigned long long)cond) << c;
                }
            }
            g_maskT[bx][i] = m;
            if (m && i < basesup) atomicOr(&s_or, m);   // contribution to colORall
        }
        __syncthreads();
        if (t == 0 && s_or) atomicOr(&g_colORall[bx], s_or);
    }
    // arrival: every block (incl. filtered/early-exit) counts exactly once
    __threadfence();
    __syncthreads();
    if (t == 0) {
        int* ctr = phase ? &g_mcount1 : &g_mcount0;
        s_last = (atomicAdd(ctr, 1) == total - 1);
    }
    __syncthreads();
    if (!s_last) return;

    // last block: run NMS over this chunk's groups (unless already done)
    if (!done) nms_run(g0, g1, out);

    if (phase) {
        // reset state for the next graph replay (runs after everything)
        __syncthreads();
        bool ok = (g_nstash >= NPRE && g_nstash <= STASH_CAP);
        for (int i = t; i < NB; i += 256) { g_alive[i] = 0ull; g_colORall[i] = 0ull; }
        if (!ok) for (int i = t; i < HB; i += 256) g_hist[i] = 0u;
        __syncthreads();
        if (t == 0) {
            g_kcount = 0; g_done = 0; g_nstash = 0;
            g_mcount0 = 0; g_mcount1 = 0;
            g_ndead = 0; g_ndovf = 0;
        }
    }
}

// ---------------- launch ----------------------------------------------------
extern "C" void kernel_launch(void* const* d_in, const int* in_sizes, int n_in,
                              void* d_out, int out_size) {
    const float* enc    = (const float*)d_in[0];  // encoded_bboxes [N,4]
    const float* anch   = (const float*)d_in[1];  // anchors        [N,4]
    const float* scores = (const float*)d_in[2];  // scores         [N]
    float* out = (float*)d_out;                   // 2000*4 boxes + 2000 scores
    int n = in_sizes[2];
    int n4 = n / 4;

    scan_stash_k<<<1024, 256>>>((const float4*)scores, n4);
    sortdecode_k<<<256, 256>>>(enc, anch, scores, n);

    // chunk 1: columns/groups [0, G1); last mask block runs NMS
    {
        dim3 grid(G1, (G1 * 64 + 255) / 256);           // (44, 11)
        masknms_k<<<grid, 256>>>(0, grid.x * grid.y, 0, G1, out, 0);
    }
    // chunk 2: columns/groups [G1, NB); usually early-exits; resets state
    {
        dim3 grid(NB - G1, (NB * 64 + 255) / 256);      // (50, 24)
        masknms_k<<<grid, 256>>>(G1, grid.x * grid.y, G1, NB, out, 1);
    }
}

// round 15
// speedup vs baseline: 1.9549x; 1.0128x over previous
#include <cuda_runtime.h>
#include <stdint.h>

// Problem constants (fixed by the reference).
#define NPRE     6000
#define NPOST    2000
#define NB       94          // ceil(NPRE/64)
#define NROWS    (NB * 64)   // 6016, padded
#define HB       32768       // score histogram buckets (scores in [0,1))
#define BCAP     256         // per-bucket sort capacity
#define SCUT     (HB - 256)  // stash cut bucket
#define STASH_CAP 32768
#define SLOCAL   256         // per-block stash buffer
#define G1       44          // chunk boundary (groups, multiple of 4)
#define NSG1     (G1 / 4)    // supergroups in chunk 1
#define NTILE1   264         // sum_{c<44} ceil((c+1)/4)
#define DCAP     1024        // dead-row list capacity

// ---------------- persistent device scratch (static zero-init at load) ------
__device__ unsigned           g_hist[HB];   // fallback path only
__device__ unsigned           g_base[HB];   // fallback path only
__device__ int                g_thresh;     // fallback path only
__device__ int                g_nstash;
__device__ int                g_scount;     // scan block counter (self-reset)
__device__ int                g_supcnt[16]; // per-supergroup mask-ready counters
__device__ int                g_mcount1;    // chunk2 arrival counter
__device__ unsigned long long g_stash[STASH_CAP];
// SoA boxes (padded rows >= NPRE are never written -> stay zero)
__device__ float              g_y1[NROWS], g_x1[NROWS], g_y2[NROWS], g_x2[NROWS];
__device__ float              g_pa[NROWS];      // 0.7f * area
__device__ float              g_scores[NROWS];
__device__ unsigned long long g_maskT[NB][NROWS];   // [col_group][row]
__device__ unsigned long long g_colORall[NB];  // OR of col words, rows < supergroup base
__device__ unsigned long long g_alive[NB];
__device__ int                g_dead[DCAP];
__device__ int                g_ndead;
__device__ int                g_ndovf;
__device__ int                g_kept[NPOST];
__device__ int                g_kcount;
__device__ int                g_done;

__device__ __forceinline__ int score_bucket(float s) {
    int b = (int)(s * 32768.0f);
    return max(0, min(HB - 1, b));
}

// ---------------- K1: scan + stash + (last block) threshold check -----------
__global__ void scan_stash_k(const float4* __restrict__ s4, int n4) {
    __shared__ unsigned long long s_stash[SLOCAL];
    __shared__ int s_scnt, s_sbase, s_last;
    __shared__ unsigned sscan[256];
    int t = threadIdx.x;                      // 256 threads
    if (t == 0) s_scnt = 0;
    __syncthreads();
    int i = blockIdx.x * blockDim.x + t;
    int stride = gridDim.x * blockDim.x;
    for (; i < n4; i += stride) {
        float4 v = s4[i];
        float e[4] = {v.x, v.y, v.z, v.w};
#pragma unroll
        for (int c = 0; c < 4; c++) {
            // s*32768 is exact (x2^15): (int)(s*32768) >= SCUT  <=>  s >= 0.9921875
            if (e[c] >= 0.9921875f) {
                unsigned idx = (unsigned)(4 * i + c);
                unsigned long long key =
                    ((unsigned long long)__float_as_uint(e[c]) << 32)
                  | (unsigned long long)(0xFFFFFFFFu - idx);
                int p = atomicAdd(&s_scnt, 1);
                if (p < SLOCAL) s_stash[p] = key;
                else {                        // rare overflow: direct global
                    int q = atomicAdd(&g_nstash, 1);
                    if (q < STASH_CAP) g_stash[q] = key;
                }
            }
        }
    }
    __syncthreads();
    int cnt = s_scnt; if (cnt > SLOCAL) cnt = SLOCAL;
    if (t == 0) s_sbase = (cnt > 0) ? atomicAdd(&g_nstash, cnt) : 0;
    __syncthreads();
    for (int k = t; k < cnt; k += 256) {
        int q = s_sbase + k;
        if (q < STASH_CAP) g_stash[q] = s_stash[k];
    }
    // ---- last-block-done: threshold check (+exact fallback, never taken) ---
    __threadfence();
    __syncthreads();
    if (t == 0) s_last = (atomicAdd(&g_scount, 1) == (int)gridDim.x - 1);
    __syncthreads();
    if (!s_last) return;
    if (t == 0) g_scount = 0;                 // self-reset for next replay
    int ns = atomicAdd(&g_nstash, 0);
    if (ns >= NPRE && ns <= STASH_CAP) return;  // fast path: nothing to do
    // fallback: full histogram + descending rank bases (256 threads)
    for (int k = t; k < n4; k += 256) {
        float4 v = s4[k];
        atomicAdd(&g_hist[score_bucket(v.x)], 1u);
        atomicAdd(&g_hist[score_bucket(v.y)], 1u);
        atomicAdd(&g_hist[score_bucket(v.z)], 1u);
        atomicAdd(&g_hist[score_bucket(v.w)], 1u);
    }
    __syncthreads();
    int lo = HB - (t + 1) * 128;              // t owns buckets [lo, lo+128)
    unsigned sum = 0;
    for (int b = 0; b < 128; b++) sum += g_hist[lo + b];
    sscan[t] = sum;
    __syncthreads();
    for (int off = 1; off < 256; off <<= 1) {
        unsigned v = (t >= off) ? sscan[t - off] : 0u;
        __syncthreads();
        sscan[t] += v;
        __syncthreads();
    }
    unsigned run = sscan[t] - sum;            // count strictly above this chunk
    for (int b = 127; b >= 0; --b) {
        unsigned c = g_hist[lo + b];
        g_base[lo + b] = run;
        if (run < (unsigned)NPRE && run + c >= (unsigned)NPRE) g_thresh = lo + b;
        run += c;
    }
    if (t == 255 && sscan[255] < (unsigned)NPRE) g_thresh = 0;
}

// ---------------- K2: per-bucket gather + sort + decode (fused) -------------
__global__ void sortdecode_k(const float* __restrict__ enc,
                             const float* __restrict__ anch,
                             const float* __restrict__ scores, int n) {
    __shared__ unsigned long long s[BCAP];
    __shared__ int s_cnt, s_above;
    int t = threadIdx.x;                      // 256 threads
    int ns = g_nstash;
    bool ok = (ns >= NPRE && ns <= STASH_CAP);

    if (ok) {
        int b = HB - 1 - blockIdx.x;          // gridDim.x == 256
        if (t == 0) { s_cnt = 0; s_above = 0; }
        __syncthreads();
        int above = 0;
        for (int i = t; i < ns; i += 256) {
            unsigned long long key = g_stash[i];
            int kb = score_bucket(__uint_as_float((unsigned)(key >> 32)));
            if (kb > b) above++;
            else if (kb == b) {
                int p = atomicAdd(&s_cnt, 1);
                if (p < BCAP) s[p] = key;
            }
        }
        if (above) atomicAdd(&s_above, above);
        __syncthreads();
        int base = s_above;
        int cnt = s_cnt; if (cnt > BCAP) cnt = BCAP;
        if (base >= NPRE || cnt == 0) return;
        int kmax = 1; while (kmax < cnt) kmax <<= 1;
        for (int i = t; i < kmax; i += 256) if (i >= cnt) s[i] = 0ull;
        __syncthreads();
        for (int k = 2; k <= kmax; k <<= 1) {
            for (int j = k >> 1; j > 0; j >>= 1) {
                for (int p = t; p < (kmax >> 1); p += 256) {
                    int i = ((p & ~(j - 1)) << 1) | (p & (j - 1));
                    int x = i | j;
                    unsigned long long a = s[i], bb = s[x];
                    bool desc = ((i & k) == 0);
                    if (desc ? (a < bb) : (a > bb)) { s[i] = bb; s[x] = a; }
                }
                __syncthreads();
            }
        }
        int lim = cnt;
        if (base + lim > NPRE) lim = NPRE - base;
        for (int i = t; i < lim; i += 256) {
            unsigned long long key = s[i];
            int r = base + i;
            float y1 = 0.f, x1 = 0.f, y2 = 0.f, x2 = 0.f, sc = 0.f;
            unsigned idx = 0xFFFFFFFFu - (unsigned)(key & 0xFFFFFFFFull);
            if (idx < (unsigned)n) {
                sc = __uint_as_float((unsigned)(key >> 32));
                float4 a = ((const float4*)anch)[idx];   // [y1, x1, y2, x2]
                float4 e = ((const float4*)enc)[idx];    // [ty, tx, th, tw]
                float ha = a.z - a.x, wa = a.w - a.y;
                float cya = a.x + 0.5f * ha, cxa = a.y + 0.5f * wa;
                float cy = e.x * ha + cya;
                float cx = e.y * wa + cxa;
                float h  = expf(e.z) * ha;
                float w  = expf(e.w) * wa;
                y1 = cy - 0.5f * h; x1 = cx - 0.5f * w;
                y2 = cy + 0.5f * h; x2 = cx + 0.5f * w;
            }
            g_y1[r] = y1; g_x1[r] = x1; g_y2[r] = y2; g_x2[r] = x2;
            g_pa[r] = 0.7f * (y2 - y1) * (x2 - x1);
            g_scores[r] = sc;
        }
        return;
    }

    // ---- exact fallback (never taken for this data) -------------------------
    int T = g_thresh;
    for (int b = T + (int)blockIdx.x; b < HB; b += gridDim.x) {
        unsigned base = g_base[b];
        if (base >= (unsigned)NPRE) continue;
        if (t == 0) s_cnt = 0;
        __syncthreads();
        for (int i = t; i < n; i += 256) {
            float sv = scores[i];
            if (score_bucket(sv) == b) {
                int p = atomicAdd(&s_cnt, 1);
                if (p < BCAP)
                    s[p] = ((unsigned long long)__float_as_uint(sv) << 32)
                         | (unsigned long long)(0xFFFFFFFFu - (unsigned)i);
            }
        }
        __syncthreads();
        int cnt = s_cnt; if (cnt > BCAP) cnt = BCAP;
        if (cnt == 0) { __syncthreads(); continue; }
        int kmax = 1; while (kmax < cnt) kmax <<= 1;
        for (int i = t; i < kmax; i += 256) if (i >= cnt) s[i] = 0ull;
        __syncthreads();
        for (int k = 2; k <= kmax; k <<= 1) {
            for (int j = k >> 1; j > 0; j >>= 1) {
                for (int p = t; p < (kmax >> 1); p += 256) {
                    int i = ((p & ~(j - 1)) << 1) | (p & (j - 1));
                    int x = i | j;
                    unsigned long long a = s[i], bb = s[x];
                    bool desc = ((i & k) == 0);
                    if (desc ? (a < bb) : (a > bb)) { s[i] = bb; s[x] = a; }
                }
                __syncthreads();
            }
        }
        int lim = cnt;
        if ((int)base + lim > NPRE) lim = NPRE - (int)base;
        for (int i = t; i < lim; i += 256) {
            unsigned long long key = s[i];
            int r = (int)base + i;
            float y1 = 0.f, x1 = 0.f, y2 = 0.f, x2 = 0.f, sc = 0.f;
            unsigned idx = 0xFFFFFFFFu - (unsigned)(key & 0xFFFFFFFFull);
            if (idx < (unsigned)n) {
                sc = __uint_as_float((unsigned)(key >> 32));
                float4 a = ((const float4*)anch)[idx];
                float4 e = ((const float4*)enc)[idx];
                float ha = a.z - a.x, wa = a.w - a.y;
                float cya = a.x + 0.5f * ha, cxa = a.y + 0.5f * wa;
                float cy = e.x * ha + cya;
                float cx = e.y * wa + cxa;
                float h  = expf(e.z) * ha;
                float w  = expf(e.w) * wa;
                y1 = cy - 0.5f * h; x1 = cx - 0.5f * w;
                y2 = cy + 0.5f * h; x2 = cx + 0.5f * w;
            }
            g_y1[r] = y1; g_x1[r] = x1; g_y2[r] = y2; g_x2[r] = x2;
            g_pa[r] = 0.7f * (y2 - y1) * (x2 - x1);
            g_scores[r] = sc;
        }
        __syncthreads();
    }
}

// ---------------- NMS over supergroups, sparse in-superstep resolution ------
// do_wait: poll per-supergroup mask-ready counters before each superstep.
__device__ void nms_run(int g0, int g1, float* __restrict__ out, int do_wait) {
    __shared__ int                s_kept[NPOST];
    __shared__ int                s_dead[DCAP];
    __shared__ unsigned long long s_alive[NB];
    __shared__ unsigned long long s_blk[4][256];
    __shared__ unsigned long long s_cross[4], s_X[4], s_Y[4], s_aliveW[4];
    __shared__ unsigned long long s_pres[4], s_keep[4];
    __shared__ int s_kc, s_nd, s_ovf;
    int t = threadIdx.x;                       // 256 threads
    int kcount = g_kcount;
    int kc0 = kcount;
    for (int i = t; i < kcount; i += 256) s_kept[i] = g_kept[i];
    for (int i = t; i < NB; i += 256) s_alive[i] = g_alive[i];
    int nd0 = g_ndead;
    for (int i = t; i < nd0 && i < DCAP; i += 256) s_dead[i] = g_dead[i];
    if (t == 0) { s_nd = nd0; s_ovf = g_ndovf; s_kc = kcount; }
    __syncthreads();

    if (g1 > NB) g1 = NB;
    for (int G = g0; G < g1; G += 4) {
        if (do_wait) {
            if (t == 0) {
                int S = G >> 2;
                int need = 4 * (S + 1);
                while (*(volatile int*)&g_supcnt[S] < need) { }
                __threadfence();
            }
            __syncthreads();
        }
        int w = g1 - G; if (w > 4) w = 4;
        int base = G * 64;
        if (t < 4) { s_cross[t] = 0ull; s_Y[t] = 0ull; s_X[t] = 0ull;
                     s_aliveW[t] = 0ull; s_pres[t] = 0ull; }
        __syncthreads();
        int c = t >> 6, lane = t & 63;
        // A1: in-block words (upper-triangular region only; rest zero)
#pragma unroll
        for (int k = 0; k < 4; k++) {
            int rp = lane + k * 64;
            unsigned long long wv = 0ull;
            if (c < w && rp < 64 * (c + 1)) wv = g_maskT[G + c][base + rp];
            s_blk[c][rp] = wv;
        }
        // A2: dead contributions Y + prefetch X = colORall
        if (c < w) {
            if (lane == 0) s_X[c] = g_colORall[G + c];
            unsigned long long p = 0ull;
            int nd = s_nd; if (nd > DCAP) nd = DCAP;
            for (int i = lane; i < nd; i += 64) p |= g_maskT[G + c][s_dead[i]];
            if (p) atomicOr(&s_Y[c], p);
        }
        __syncthreads();
        // presence bitmap of rows with any in-superstep suppression word
        {
            unsigned long long rowOR = s_blk[0][t] | s_blk[1][t]
                                     | s_blk[2][t] | s_blk[3][t];
            if (rowOR) atomicOr(&s_pres[t >> 6], 1ull << (t & 63));
        }
        bool ovf = (s_ovf != 0) || (s_nd > DCAP);
        if (t < 4) s_cross[t] = ((s_Y[t] == 0ull) && !ovf) ? s_X[t] : 0ull;
        __syncthreads();
        // rare: exact full scan for columns with dead contributions
        for (int cc = 0; cc < w; cc++) {
            if ((s_Y[cc] != 0ull) || ovf) {
                const unsigned long long* colp_ = g_maskT[G + cc];
                unsigned long long p = 0ull;
                for (int r = t; r < base; r += 256)
                    p |= colp_[r] & (0ull - ((s_alive[r >> 6] >> (r & 63)) & 1ull));
                if (p) atomicOr(&s_cross[cc], p);
            }
        }
        __syncthreads();
        // resolve: common case zero presence -> keep = ~cross; else thread 0
        // walks the (tiny) set of suppressor rows in ascending order.
        unsigned long long anynz = s_pres[0] | s_pres[1] | s_pres[2] | s_pres[3];
        if (anynz == 0ull) {
            if (t < 4) {
                int nn = NPRE - (base + t * 64);
                nn = nn < 0 ? 0 : (nn > 64 ? 64 : nn);
                unsigned long long rm = (nn == 64) ? ~0ull
                                       : ((nn == 0) ? 0ull : ((1ull << nn) - 1ull));
                s_keep[t] = (t < w) ? ((~s_cross[t]) & rm) : 0ull;
            }
        } else if (t == 0) {
            unsigned long long alive[4];
#pragma unroll
            for (int cc = 0; cc < 4; cc++) {
                int nn = NPRE - (base + cc * 64);
                nn = nn < 0 ? 0 : (nn > 64 ? 64 : nn);
                unsigned long long rm = (nn == 64) ? ~0ull
                                       : ((nn == 0) ? 0ull : ((1ull << nn) - 1ull));
                alive[cc] = (cc < w) ? ((~s_cross[cc]) & rm) : 0ull;
            }
#pragma unroll
            for (int w64 = 0; w64 < 4; w64++) {
                unsigned long long pres = s_pres[w64];
                while (pres) {
                    int b_ = __ffsll((long long)pres) - 1;
                    pres &= pres - 1;
                    int rp = w64 * 64 + b_;
                    if ((alive[rp >> 6] >> (rp & 63)) & 1ull) {
                        alive[0] &= ~s_blk[0][rp];
                        alive[1] &= ~s_blk[1][rp];
                        alive[2] &= ~s_blk[2][rp];
                        alive[3] &= ~s_blk[3][rp];
                    }
                }
            }
            s_keep[0] = alive[0]; s_keep[1] = alive[1];
            s_keep[2] = alive[2]; s_keep[3] = alive[3];
        }
        __syncthreads();
        // emit (common): rank-ordered parallel write
        int budget = NPOST - kcount;
        int pc0 = __popcll(s_keep[0]), pc1 = __popcll(s_keep[1]);
        int pc2 = __popcll(s_keep[2]), pc3 = __popcll(s_keep[3]);
        if ((s_keep[c] >> lane) & 1ull) {
            int off = (c > 0 ? pc0 : 0) + (c > 1 ? pc1 : 0) + (c > 2 ? pc2 : 0);
            int rank = off + __popcll(s_keep[c] & ((1ull << lane) - 1ull));
            if (rank < budget) {
                s_kept[kcount + rank] = base + t;
                atomicOr(&s_aliveW[c], 1ull << lane);
            }
        }
        if (t == 0) {
            int tot = pc0 + pc1 + pc2 + pc3;
            s_kc = kcount + (tot < budget ? tot : budget);
        }
        __syncthreads();
        kcount = s_kc;
        // C: commit alive + append dead rows
        if (t < 4 && t < w) s_alive[G + t] = s_aliveW[t];
        bool fin = (kcount >= NPOST);
        if (!fin && c < w) {
            int row = base + t;
            if (row < NPRE && !((s_aliveW[c] >> lane) & 1ull)) {
                int p = atomicAdd(&s_nd, 1);
                if (p < DCAP) s_dead[p] = row;
                else s_ovf = 1;
            }
        }
        __syncthreads();
        if (fin) break;
    }

    bool finished = (kcount >= NPOST) || (g1 >= NB);
    if (finished) {
        for (int o = t; o < NPOST; o += 256) {
            if (o < kcount) {
                int i = s_kept[o];
                ((float4*)out)[o] = make_float4(g_y1[i], g_x1[i], g_y2[i], g_x2[i]);
                out[NPOST * 4 + o] = g_scores[i];
            } else {
                ((float4*)out)[o] = make_float4(0.f, 0.f, 0.f, 0.f);
                out[NPOST * 4 + o] = 0.f;
            }
        }
        __syncthreads();
        if (t == 0) { __threadfence(); g_done = 1; }
    } else {
        for (int i = kc0 + t; i < kcount; i += 256) g_kept[i] = s_kept[i];
        for (int i = t; i < NB; i += 256) g_alive[i] = s_alive[i];
        int nd = s_nd; if (nd > DCAP) nd = DCAP;
        for (int i = nd0 + t; i < nd; i += 256) g_dead[i] = s_dead[i];
        if (t == 0) { g_kcount = kcount; g_ndead = s_nd; g_ndovf = s_ovf; }
    }
}

// ---------------- K3: chunk-1 overlapped mask producers + NMS consumer ------
// iou > 0.7  <=>  1.7*inter > 0.7*areaA + 0.7*areaB
__global__ void masknms1_k(float* __restrict__ out) {
    int t = threadIdx.x;                      // 256 threads
    if (blockIdx.x == 0) {                    // consumer: scheduled first
        nms_run(0, G1, out, /*do_wait=*/1);
        return;
    }
    // producer: flat ticket -> (column c, row-tile rb)
    int tau = (int)blockIdx.x - 1;            // [0, NTILE1)
    int c = 0, cum = 0;
    while (true) {
        int tc = (c >> 2) + 1;
        if (tau < cum + tc) break;
        cum += tc; c++;
    }
    int rb = tau - cum;

    __shared__ float4 colb[64];
    __shared__ float  colp[64];
    __shared__ unsigned long long s_or;
    if (t == 0) s_or = 0ull;
    if (t < 64) {
        int j = c * 64 + t;
        colb[t] = make_float4(g_y1[j], g_x1[j], g_y2[j], g_x2[j]);
        colp[t] = g_pa[j];
    }
    __syncthreads();
    int rowlim = (c + 1) * 64;
    int basesup = (c & ~3) * 64;
    int i = rb * 256 + t;
    if (i < rowlim) {
        float y1 = g_y1[i], x1 = g_x1[i], y2 = g_y2[i], x2 = g_x2[i];
        float pa = g_pa[i];
        unsigned long long m = 0ull;
        int c0 = i - c * 64 + 1;              // >0 only on the diagonal group
        if (c0 <= 0) {
#pragma unroll 16
            for (int cc = 0; cc < 64; cc++) {
                float4 cb = colb[cc];
                float iy1 = fmaxf(y1, cb.x), ix1 = fmaxf(x1, cb.y);
                float iy2 = fminf(y2, cb.z), ix2 = fminf(x2, cb.w);
                float dy = fmaxf(iy2 - iy1, 0.f), dx = fmaxf(ix2 - ix1, 0.f);
                bool cond = fmaf(1.7f, dy * dx, -pa) > colp[cc];
                m |= ((unsigned long long)cond) << cc;
            }
        } else {
            for (int cc = c0; cc < 64; cc++) {
                float4 cb = colb[cc];
                float iy1 = fmaxf(y1, cb.x), ix1 = fmaxf(x1, cb.y);
                float iy2 = fminf(y2, cb.z), ix2 = fminf(x2, cb.w);
                float dy = fmaxf(iy2 - iy1, 0.f), dx = fmaxf(ix2 - ix1, 0.f);
                bool cond = fmaf(1.7f, dy * dx, -pa) > colp[cc];
                m |= ((unsigned long long)cond) << cc;
            }
        }
        g_maskT[c][i] = m;
        if (m && i < basesup) atomicOr(&s_or, m);
    }
    __threadfence();                           // publish mask words
    __syncthreads();
    if (t == 0) {
        if (s_or) atomicOr(&g_colORall[c], s_or);
        __threadfence();
        atomicAdd(&g_supcnt[c >> 2], 1);       // signal readiness
    }
}

// ---------------- K4: chunk-2 mask (4 row-tiles/block) + last-block NMS -----
__global__ void masknms2_k(int total, float* __restrict__ out) {
    int done = *(volatile int*)&g_done;
    int bx = G1 + (int)blockIdx.x;            // columns [G1, NB)
    int by = blockIdx.y;
    int t = threadIdx.x;                      // 256 threads
    __shared__ float4 colb[64];
    __shared__ float  colp[64];
    __shared__ unsigned long long s_or;
    __shared__ int s_last;

    int rowlim = (bx + 1) * 64;
    if (!done && by * 1024 < rowlim) {
        if (t == 0) s_or = 0ull;
        if (t < 64) {
            int j = bx * 64 + t;
            colb[t] = make_float4(g_y1[j], g_x1[j], g_y2[j], g_x2[j]);
            colp[t] = g_pa[j];
        }
        __syncthreads();
        int basesup = (bx & ~3) * 64;
        unsigned long long orloc = 0ull;
        for (int k = 0; k < 4; k++) {
            int i = by * 1024 + k * 256 + t;
            if (i >= rowlim) break;
            float y1 = g_y1[i], x1 = g_x1[i], y2 = g_y2[i], x2 = g_x2[i];
            float pa = g_pa[i];
            unsigned long long m = 0ull;
            int c0 = i - bx * 64 + 1;
            if (c0 <= 0) {
#pragma unroll 16
                for (int cc = 0; cc < 64; cc++) {
                    float4 cb = colb[cc];
                    float iy1 = fmaxf(y1, cb.x), ix1 = fmaxf(x1, cb.y);
                    float iy2 = fminf(y2, cb.z), ix2 = fminf(x2, cb.w);
                    float dy = fmaxf(iy2 - iy1, 0.f), dx = fmaxf(ix2 - ix1, 0.f);
                    bool cond = fmaf(1.7f, dy * dx, -pa) > colp[cc];
                    m |= ((unsigned long long)cond) << cc;
                }
            } else {
                for (int cc = c0; cc < 64; cc++) {
                    float4 cb = colb[cc];
                    float iy1 = fmaxf(y1, cb.x), ix1 = fmaxf(x1, cb.y);
                    float iy2 = fminf(y2, cb.z), ix2 = fminf(x2, cb.w);
                    float dy = fmaxf(iy2 - iy1, 0.f), dx = fmaxf(ix2 - ix1, 0.f);
                    bool cond = fmaf(1.7f, dy * dx, -pa) > colp[cc];
                    m |= ((unsigned long long)cond) << cc;
                }
            }
            g_maskT[bx][i] = m;
            if (m && i < basesup) orloc |= m;
        }
        if (orloc) atomicOr(&s_or, orloc);
        __syncthreads();
        if (t == 0 && s_or) atomicOr(&g_colORall[bx], s_or);
    }
    // arrival: every block counts exactly once
    __threadfence();
    __syncthreads();
    if (t == 0) s_last = (atomicAdd(&g_mcount1, 1) == total - 1);
    __syncthreads();
    if (!s_last) return;

    if (!done && !(*(volatile int*)&g_done))
        nms_run(G1, NB, out, /*do_wait=*/0);

    // reset state for the next graph replay
    __syncthreads();
    bool ok = (g_nstash >= NPRE && g_nstash <= STASH_CAP);
    for (int i = t; i < NB; i += 256) { g_alive[i] = 0ull; g_colORall[i] = 0ull; }
    if (t < 16) g_supcnt[t] = 0;
    if (!ok) for (int i = t; i < HB; i += 256) g_hist[i] = 0u;
    __syncthreads();
    if (t == 0) {
        g_kcount = 0; g_done = 0; g_nstash = 0;
        g_mcount1 = 0; g_ndead = 0; g_ndovf = 0;
    }
}

// ---------------- launch ----------------------------------------------------
extern "C" void kernel_launch(void* const* d_in, const int* in_sizes, int n_in,
                              void* d_out, int out_size) {
    const float* enc    = (const float*)d_in[0];  // encoded_bboxes [N,4]
    const float* anch   = (const float*)d_in[1];  // anchors        [N,4]
    const float* scores = (const float*)d_in[2];  // scores         [N]
    float* out = (float*)d_out;                   // 2000*4 boxes + 2000 scores
    int n = in_sizes[2];
    int n4 = n / 4;

    scan_stash_k<<<1024, 256>>>((const float4*)scores, n4);
    sortdecode_k<<<256, 256>>>(enc, anch, scores, n);

    // chunk 1: overlapped producers + consumer (block 0 = NMS)
    masknms1_k<<<NTILE1 + 1, 256>>>(out);

    // chunk 2: fallback for exit > G1; usually ghost; resets state
    {
        dim3 grid(NB - G1, (NB * 64 + 1023) / 1024);    // (50, 6)
        masknms2_k<<<grid, 256>>>(grid.x * grid.y, out);
    }
}

// round 16
// speedup vs baseline: 2.2578x; 1.1549x over previous
#include <cuda_runtime.h>
#include <stdint.h>

// Problem constants (fixed by the reference).
#define NPRE     6000
#define NPOST    2000
#define NB       94          // ceil(NPRE/64)
#define NROWS    (NB * 64)   // 6016, padded
#define HB       32768       // score histogram buckets (scores in [0,1))
#define BCAP     256         // per-bucket sort capacity
#define NBKT     256         // number of top buckets tracked (HB-SCUT)
#define SCUT     (HB - NBKT) // stash cut bucket
#define STASH_CAP 32768
#define SLOCAL   256         // per-block stash buffer
#define G1       44          // chunk boundary (groups, multiple of 4)
#define NTILE1   264         // sum_{c<44} ceil((c+1)/4)
#define DCAP     1024        // dead-row list capacity

// ---------------- persistent device scratch (static zero-init at load) ------
__device__ unsigned           g_hist[HB];   // fallback path only
__device__ unsigned           g_base[HB];   // fallback path only
__device__ int                g_thresh;     // fallback path only
__device__ int                g_nstash;
__device__ int                g_scount;     // scan block counter (self-reset)
__device__ int                g_supcnt[16]; // per-supergroup mask-ready counters
__device__ int                g_mcount1;    // chunk2 arrival counter
__device__ unsigned long long g_stash[STASH_CAP];
__device__ int                g_bcnt[NBKT];               // per-bucket counts (exact)
__device__ unsigned long long g_bcand[NBKT * BCAP];       // per-bucket keys
// SoA boxes (padded rows >= NPRE are never written -> stay zero)
__device__ float              g_y1[NROWS], g_x1[NROWS], g_y2[NROWS], g_x2[NROWS];
__device__ float              g_pa[NROWS];      // 0.7f * area
__device__ float              g_scores[NROWS];
__device__ unsigned long long g_maskT[NB][NROWS];   // [col_group][row]
__device__ unsigned long long g_colORall[NB];  // OR of col words, rows < supergroup base
__device__ unsigned long long g_alive[NB];
__device__ int                g_dead[DCAP];
__device__ int                g_ndead;
__device__ int                g_ndovf;
__device__ int                g_kept[NPOST];
__device__ int                g_kcount;
__device__ int                g_done;

__device__ __forceinline__ int score_bucket(float s) {
    int b = (int)(s * 32768.0f);
    return max(0, min(HB - 1, b));
}

// scatter one key into its per-bucket slot (counts are exact even on overflow)
__device__ __forceinline__ void bucket_scatter(unsigned long long key) {
    int b = score_bucket(__uint_as_float((unsigned)(key >> 32)));
    int rb = b - SCUT;
    if (rb >= 0) {
        int pos = atomicAdd(&g_bcnt[rb], 1);
        if (pos < BCAP) g_bcand[rb * BCAP + pos] = key;
    }
}

// ---------------- K1: scan + stash + bucket scatter + threshold check -------
__global__ void scan_stash_k(const float4* __restrict__ s4, int n4) {
    __shared__ unsigned long long s_stash[SLOCAL];
    __shared__ int s_scnt, s_sbase, s_last;
    __shared__ unsigned sscan[256];
    int t = threadIdx.x;                      // 256 threads
    if (t == 0) s_scnt = 0;
    __syncthreads();
    int i = blockIdx.x * blockDim.x + t;
    int stride = gridDim.x * blockDim.x;
    for (; i < n4; i += stride) {
        float4 v = s4[i];
        float e[4] = {v.x, v.y, v.z, v.w};
#pragma unroll
        for (int c = 0; c < 4; c++) {
            // s*32768 is exact (x2^15): (int)(s*32768) >= SCUT  <=>  s >= 0.9921875
            if (e[c] >= 0.9921875f) {
                unsigned idx = (unsigned)(4 * i + c);
                unsigned long long key =
                    ((unsigned long long)__float_as_uint(e[c]) << 32)
                  | (unsigned long long)(0xFFFFFFFFu - idx);
                int p = atomicAdd(&s_scnt, 1);
                if (p < SLOCAL) s_stash[p] = key;
                else {                        // rare overflow: direct global
                    int q = atomicAdd(&g_nstash, 1);
                    if (q < STASH_CAP) g_stash[q] = key;
                    bucket_scatter(key);
                }
            }
        }
    }
    __syncthreads();
    int cnt = s_scnt; if (cnt > SLOCAL) cnt = SLOCAL;
    if (t == 0) s_sbase = (cnt > 0) ? atomicAdd(&g_nstash, cnt) : 0;
    __syncthreads();
    for (int k = t; k < cnt; k += 256) {
        unsigned long long key = s_stash[k];
        int q = s_sbase + k;
        if (q < STASH_CAP) g_stash[q] = key;
        bucket_scatter(key);
    }
    // ---- last-block-done: threshold check (+exact fallback, never taken) ---
    __threadfence();
    __syncthreads();
    if (t == 0) s_last = (atomicAdd(&g_scount, 1) == (int)gridDim.x - 1);
    __syncthreads();
    if (!s_last) return;
    if (t == 0) g_scount = 0;                 // self-reset for next replay
    int ns = atomicAdd(&g_nstash, 0);
    if (ns >= NPRE && ns <= STASH_CAP) return;  // fast path: nothing to do
    // fallback: full histogram + descending rank bases (256 threads)
    for (int k = t; k < n4; k += 256) {
        float4 v = s4[k];
        atomicAdd(&g_hist[score_bucket(v.x)], 1u);
        atomicAdd(&g_hist[score_bucket(v.y)], 1u);
        atomicAdd(&g_hist[score_bucket(v.z)], 1u);
        atomicAdd(&g_hist[score_bucket(v.w)], 1u);
    }
    __syncthreads();
    int lo = HB - (t + 1) * 128;              // t owns buckets [lo, lo+128)
    unsigned sum = 0;
    for (int b = 0; b < 128; b++) sum += g_hist[lo + b];
    sscan[t] = sum;
    __syncthreads();
    for (int off = 1; off < 256; off <<= 1) {
        unsigned v = (t >= off) ? sscan[t - off] : 0u;
        __syncthreads();
        sscan[t] += v;
        __syncthreads();
    }
    unsigned run = sscan[t] - sum;            // count strictly above this chunk
    for (int b = 127; b >= 0; --b) {
        unsigned c = g_hist[lo + b];
        g_base[lo + b] = run;
        if (run < (unsigned)NPRE && run + c >= (unsigned)NPRE) g_thresh = lo + b;
        run += c;
    }
    if (t == 255 && sscan[255] < (unsigned)NPRE) g_thresh = 0;
}

// ---------------- K2: per-bucket sort + decode (direct bucket read) ---------
__global__ void sortdecode_k(const float* __restrict__ enc,
                             const float* __restrict__ anch,
                             const float* __restrict__ scores, int n) {
    __shared__ unsigned long long s[BCAP];
    __shared__ int s_cnt, s_above;
    int t = threadIdx.x;                      // 256 threads
    int ns = g_nstash;
    bool ok = (ns >= NPRE && ns <= STASH_CAP);

    if (ok) {
        int rb = NBKT - 1 - (int)blockIdx.x;  // bucket row; gridDim.x == NBKT
        int b = SCUT + rb;
        if (t == 0) { s_cnt = 0; s_above = 0; }
        __syncthreads();
        // base = count of keys in strictly higher buckets; mycnt from counters
        int cthis = g_bcnt[t];                // thread t reads bucket row t
        if (t > rb && cthis) atomicAdd(&s_above, cthis);
        __syncthreads();
        int base = s_above;
        int mycnt = g_bcnt[rb];
        if (base >= NPRE || mycnt == 0) return;
        int cnt = (mycnt < BCAP) ? mycnt : BCAP;
        if (mycnt <= BCAP) {
            for (int i = t; i < cnt; i += 256) s[i] = g_bcand[rb * BCAP + i];
            __syncthreads();
        } else {
            // per-bucket fallback (~never): gather from stash, capped at BCAP
            for (int i = t; i < ns; i += 256) {
                unsigned long long key = g_stash[i];
                int kb = score_bucket(__uint_as_float((unsigned)(key >> 32)));
                if (kb == b) {
                    int p = atomicAdd(&s_cnt, 1);
                    if (p < BCAP) s[p] = key;
                }
            }
            __syncthreads();
            cnt = s_cnt; if (cnt > BCAP) cnt = BCAP;
        }
        int kmax = 1; while (kmax < cnt) kmax <<= 1;
        for (int i = t; i < kmax; i += 256) if (i >= cnt) s[i] = 0ull;
        __syncthreads();
        for (int k = 2; k <= kmax; k <<= 1) {
            for (int j = k >> 1; j > 0; j >>= 1) {
                for (int p = t; p < (kmax >> 1); p += 256) {
                    int i = ((p & ~(j - 1)) << 1) | (p & (j - 1));
                    int x = i | j;
                    unsigned long long a = s[i], bb = s[x];
                    bool desc = ((i & k) == 0);
                    if (desc ? (a < bb) : (a > bb)) { s[i] = bb; s[x] = a; }
                }
                __syncthreads();
            }
        }
        int lim = cnt;
        if (base + lim > NPRE) lim = NPRE - base;
        for (int i = t; i < lim; i += 256) {
            unsigned long long key = s[i];
            int r = base + i;
            float y1 = 0.f, x1 = 0.f, y2 = 0.f, x2 = 0.f, sc = 0.f;
            unsigned idx = 0xFFFFFFFFu - (unsigned)(key & 0xFFFFFFFFull);
            if (idx < (unsigned)n) {
                sc = __uint_as_float((unsigned)(key >> 32));
                float4 a = ((const float4*)anch)[idx];   // [y1, x1, y2, x2]
                float4 e = ((const float4*)enc)[idx];    // [ty, tx, th, tw]
                float ha = a.z - a.x, wa = a.w - a.y;
                float cya = a.x + 0.5f * ha, cxa = a.y + 0.5f * wa;
                float cy = e.x * ha + cya;
                float cx = e.y * wa + cxa;
                float h  = expf(e.z) * ha;
                float w  = expf(e.w) * wa;
                y1 = cy - 0.5f * h; x1 = cx - 0.5f * w;
                y2 = cy + 0.5f * h; x2 = cx + 0.5f * w;
            }
            g_y1[r] = y1; g_x1[r] = x1; g_y2[r] = y2; g_x2[r] = x2;
            g_pa[r] = 0.7f * (y2 - y1) * (x2 - x1);
            g_scores[r] = sc;
        }
        return;
    }

    // ---- exact fallback (never taken for this data) -------------------------
    int T = g_thresh;
    for (int b = T + (int)blockIdx.x; b < HB; b += gridDim.x) {
        unsigned base = g_base[b];
        if (base >= (unsigned)NPRE) continue;
        if (t == 0) s_cnt = 0;
        __syncthreads();
        for (int i = t; i < n; i += 256) {
            float sv = scores[i];
            if (score_bucket(sv) == b) {
                int p = atomicAdd(&s_cnt, 1);
                if (p < BCAP)
                    s[p] = ((unsigned long long)__float_as_uint(sv) << 32)
                         | (unsigned long long)(0xFFFFFFFFu - (unsigned)i);
            }
        }
        __syncthreads();
        int cnt = s_cnt; if (cnt > BCAP) cnt = BCAP;
        if (cnt == 0) { __syncthreads(); continue; }
        int kmax = 1; while (kmax < cnt) kmax <<= 1;
        for (int i = t; i < kmax; i += 256) if (i >= cnt) s[i] = 0ull;
        __syncthreads();
        for (int k = 2; k <= kmax; k <<= 1) {
            for (int j = k >> 1; j > 0; j >>= 1) {
                for (int p = t; p < (kmax >> 1); p += 256) {
                    int i = ((p & ~(j - 1)) << 1) | (p & (j - 1));
                    int x = i | j;
                    unsigned long long a = s[i], bb = s[x];
                    bool desc = ((i & k) == 0);
                    if (desc ? (a < bb) : (a > bb)) { s[i] = bb; s[x] = a; }
                }
                __syncthreads();
            }
        }
        int lim = cnt;
        if ((int)base + lim > NPRE) lim = NPRE - (int)base;
        for (int i = t; i < lim; i += 256) {
            unsigned long long key = s[i];
            int r = (int)base + i;
            float y1 = 0.f, x1 = 0.f, y2 = 0.f, x2 = 0.f, sc = 0.f;
            unsigned idx = 0xFFFFFFFFu - (unsigned)(key & 0xFFFFFFFFull);
            if (idx < (unsigned)n) {
                sc = __uint_as_float((unsigned)(key >> 32));
                float4 a = ((const float4*)anch)[idx];
                float4 e = ((const float4*)enc)[idx];
                float ha = a.z - a.x, wa = a.w - a.y;
                float cya = a.x + 0.5f * ha, cxa = a.y + 0.5f * wa;
                float cy = e.x * ha + cya;
                float cx = e.y * wa + cxa;
                float h  = expf(e.z) * ha;
                float w  = expf(e.w) * wa;
                y1 = cy - 0.5f * h; x1 = cx - 0.5f * w;
                y2 = cy + 0.5f * h; x2 = cx + 0.5f * w;
            }
            g_y1[r] = y1; g_x1[r] = x1; g_y2[r] = y2; g_x2[r] = x2;
            g_pa[r] = 0.7f * (y2 - y1) * (x2 - x1);
            g_scores[r] = sc;
        }
        __syncthreads();
    }
}

// ---------------- NMS over supergroups, sparse in-superstep resolution ------
__device__ void nms_run(int g0, int g1, float* __restrict__ out, int do_wait) {
    __shared__ int                s_kept[NPOST];
    __shared__ int                s_dead[DCAP];
    __shared__ unsigned long long s_alive[NB];
    __shared__ unsigned long long s_blk[4][256];
    __shared__ unsigned long long s_cross[4], s_X[4], s_Y[4], s_aliveW[4];
    __shared__ unsigned long long s_pres[4], s_keep[4];
    __shared__ int s_kc, s_nd, s_ovf;
    int t = threadIdx.x;                       // 256 threads
    int kcount = g_kcount;
    int kc0 = kcount;
    for (int i = t; i < kcount; i += 256) s_kept[i] = g_kept[i];
    for (int i = t; i < NB; i += 256) s_alive[i] = g_alive[i];
    int nd0 = g_ndead;
    for (int i = t; i < nd0 && i < DCAP; i += 256) s_dead[i] = g_dead[i];
    if (t == 0) { s_nd = nd0; s_ovf = g_ndovf; s_kc = kcount; }
    __syncthreads();

    if (g1 > NB) g1 = NB;
    for (int G = g0; G < g1; G += 4) {
        if (do_wait) {
            if (t == 0) {
                int S = G >> 2;
                int need = 4 * (S + 1);
                while (*(volatile int*)&g_supcnt[S] < need) { }
                __threadfence();
            }
            __syncthreads();
        }
        int w = g1 - G; if (w > 4) w = 4;
        int base = G * 64;
        if (t < 4) { s_cross[t] = 0ull; s_Y[t] = 0ull; s_X[t] = 0ull;
                     s_aliveW[t] = 0ull; s_pres[t] = 0ull; }
        __syncthreads();
        int c = t >> 6, lane = t & 63;
#pragma unroll
        for (int k = 0; k < 4; k++) {
            int rp = lane + k * 64;
            unsigned long long wv = 0ull;
            if (c < w && rp < 64 * (c + 1)) wv = g_maskT[G + c][base + rp];
            s_blk[c][rp] = wv;
        }
        if (c < w) {
            if (lane == 0) s_X[c] = g_colORall[G + c];
            unsigned long long p = 0ull;
            int nd = s_nd; if (nd > DCAP) nd = DCAP;
            for (int i = lane; i < nd; i += 64) p |= g_maskT[G + c][s_dead[i]];
            if (p) atomicOr(&s_Y[c], p);
        }
        __syncthreads();
        {
            unsigned long long rowOR = s_blk[0][t] | s_blk[1][t]
                                     | s_blk[2][t] | s_blk[3][t];
            if (rowOR) atomicOr(&s_pres[t >> 6], 1ull << (t & 63));
        }
        bool ovf = (s_ovf != 0) || (s_nd > DCAP);
        if (t < 4) s_cross[t] = ((s_Y[t] == 0ull) && !ovf) ? s_X[t] : 0ull;
        __syncthreads();
        for (int cc = 0; cc < w; cc++) {
            if ((s_Y[cc] != 0ull) || ovf) {
                const unsigned long long* colp_ = g_maskT[G + cc];
                unsigned long long p = 0ull;
                for (int r = t; r < base; r += 256)
                    p |= colp_[r] & (0ull - ((s_alive[r >> 6] >> (r & 63)) & 1ull));
                if (p) atomicOr(&s_cross[cc], p);
            }
        }
        __syncthreads();
        unsigned long long anynz = s_pres[0] | s_pres[1] | s_pres[2] | s_pres[3];
        if (anynz == 0ull) {
            if (t < 4) {
                int nn = NPRE - (base + t * 64);
                nn = nn < 0 ? 0 : (nn > 64 ? 64 : nn);
                unsigned long long rm = (nn == 64) ? ~0ull
                                       : ((nn == 0) ? 0ull : ((1ull << nn) - 1ull));
                s_keep[t] = (t < w) ? ((~s_cross[t]) & rm) : 0ull;
            }
        } else if (t == 0) {
            unsigned long long alive[4];
#pragma unroll
            for (int cc = 0; cc < 4; cc++) {
                int nn = NPRE - (base + cc * 64);
                nn = nn < 0 ? 0 : (nn > 64 ? 64 : nn);
                unsigned long long rm = (nn == 64) ? ~0ull
                                       : ((nn == 0) ? 0ull : ((1ull << nn) - 1ull));
                alive[cc] = (cc < w) ? ((~s_cross[cc]) & rm) : 0ull;
            }
#pragma unroll
            for (int w64 = 0; w64 < 4; w64++) {
                unsigned long long pres = s_pres[w64];
                while (pres) {
                    int b_ = __ffsll((long long)pres) - 1;
                    pres &= pres - 1;
                    int rp = w64 * 64 + b_;
                    if ((alive[rp >> 6] >> (rp & 63)) & 1ull) {
                        alive[0] &= ~s_blk[0][rp];
                        alive[1] &= ~s_blk[1][rp];
                        alive[2] &= ~s_blk[2][rp];
                        alive[3] &= ~s_blk[3][rp];
                    }
                }
            }
            s_keep[0] = alive[0]; s_keep[1] = alive[1];
            s_keep[2] = alive[2]; s_keep[3] = alive[3];
        }
        __syncthreads();
        int budget = NPOST - kcount;
        int pc0 = __popcll(s_keep[0]), pc1 = __popcll(s_keep[1]);
        int pc2 = __popcll(s_keep[2]), pc3 = __popcll(s_keep[3]);
        if ((s_keep[c] >> lane) & 1ull) {
            int off = (c > 0 ? pc0 : 0) + (c > 1 ? pc1 : 0) + (c > 2 ? pc2 : 0);
            int rank = off + __popcll(s_keep[c] & ((1ull << lane) - 1ull));
            if (rank < budget) {
                s_kept[kcount + rank] = base + t;
                atomicOr(&s_aliveW[c], 1ull << lane);
            }
        }
        if (t == 0) {
            int tot = pc0 + pc1 + pc2 + pc3;
            s_kc = kcount + (tot < budget ? tot : budget);
        }
        __syncthreads();
        kcount = s_kc;
        if (t < 4 && t < w) s_alive[G + t] = s_aliveW[t];
        bool fin = (kcount >= NPOST);
        if (!fin && c < w) {
            int row = base + t;
            if (row < NPRE && !((s_aliveW[c] >> lane) & 1ull)) {
                int p = atomicAdd(&s_nd, 1);
                if (p < DCAP) s_dead[p] = row;
                else s_ovf = 1;
            }
        }
        __syncthreads();
        if (fin) break;
    }

    bool finished = (kcount >= NPOST) || (g1 >= NB);
    if (finished) {
        for (int o = t; o < NPOST; o += 256) {
            if (o < kcount) {
                int i = s_kept[o];
                ((float4*)out)[o] = make_float4(g_y1[i], g_x1[i], g_y2[i], g_x2[i]);
                out[NPOST * 4 + o] = g_scores[i];
            } else {
                ((float4*)out)[o] = make_float4(0.f, 0.f, 0.f, 0.f);
                out[NPOST * 4 + o] = 0.f;
            }
        }
        __syncthreads();
        if (t == 0) { __threadfence(); g_done = 1; }
    } else {
        for (int i = kc0 + t; i < kcount; i += 256) g_kept[i] = s_kept[i];
        for (int i = t; i < NB; i += 256) g_alive[i] = s_alive[i];
        int nd = s_nd; if (nd > DCAP) nd = DCAP;
        for (int i = nd0 + t; i < nd; i += 256) g_dead[i] = s_dead[i];
        if (t == 0) { g_kcount = kcount; g_ndead = s_nd; g_ndovf = s_ovf; }
    }
}

// ---------------- K3: chunk-1 overlapped mask producers + NMS consumer ------
// iou > 0.7  <=>  1.7*inter > 0.7*areaA + 0.7*areaB
__global__ void masknms1_k(float* __restrict__ out) {
    int t = threadIdx.x;                      // 256 threads
    if (blockIdx.x == 0) {                    // consumer: scheduled first
        nms_run(0, G1, out, /*do_wait=*/1);
        return;
    }
    int tau = (int)blockIdx.x - 1;            // [0, NTILE1)
    int c = 0, cum = 0;
    while (true) {
        int tc = (c >> 2) + 1;
        if (tau < cum + tc) break;
        cum += tc; c++;
    }
    int rb = tau - cum;

    __shared__ float4 colb[64];
    __shared__ float  colp[64];
    __shared__ unsigned long long s_or;
    if (t == 0) s_or = 0ull;
    if (t < 64) {
        int j = c * 64 + t;
        colb[t] = make_float4(g_y1[j], g_x1[j], g_y2[j], g_x2[j]);
        colp[t] = g_pa[j];
    }
    __syncthreads();
    int rowlim = (c + 1) * 64;
    int basesup = (c & ~3) * 64;
    int i = rb * 256 + t;
    if (i < rowlim) {
        float y1 = g_y1[i], x1 = g_x1[i], y2 = g_y2[i], x2 = g_x2[i];
        float pa = g_pa[i];
        unsigned long long m = 0ull;
        int c0 = i - c * 64 + 1;              // >0 only on the diagonal group
        if (c0 <= 0) {
#pragma unroll 16
            for (int cc = 0; cc < 64; cc++) {
                float4 cb = colb[cc];
                float iy1 = fmaxf(y1, cb.x), ix1 = fmaxf(x1, cb.y);
                float iy2 = fminf(y2, cb.z), ix2 = fminf(x2, cb.w);
                float dy = fmaxf(iy2 - iy1, 0.f), dx = fmaxf(ix2 - ix1, 0.f);
                bool cond = fmaf(1.7f, dy * dx, -pa) > colp[cc];
                m |= ((unsigned long long)cond) << cc;
            }
        } else {
            for (int cc = c0; cc < 64; cc++) {
                float4 cb = colb[cc];
                float iy1 = fmaxf(y1, cb.x), ix1 = fmaxf(x1, cb.y);
                float iy2 = fminf(y2, cb.z), ix2 = fminf(x2, cb.w);
                float dy = fmaxf(iy2 - iy1, 0.f), dx = fmaxf(ix2 - ix1, 0.f);
                bool cond = fmaf(1.7f, dy * dx, -pa) > colp[cc];
                m |= ((unsigned long long)cond) << cc;
            }
        }
        g_maskT[c][i] = m;
        if (m && i < basesup) atomicOr(&s_or, m);
    }
    __threadfence();                           // publish mask words
    __syncthreads();
    if (t == 0) {
        if (s_or) atomicOr(&g_colORall[c], s_or);
        __threadfence();
        atomicAdd(&g_supcnt[c >> 2], 1);       // signal readiness
    }
}

// ---------------- K4: chunk-2 mask (8 row-tiles/block) + last-block NMS -----
__global__ void masknms2_k(int total, float* __restrict__ out) {
    int done = *(volatile int*)&g_done;
    int bx = G1 + (int)blockIdx.x;            // columns [G1, NB)
    int by = blockIdx.y;
    int t = threadIdx.x;                      // 256 threads
    __shared__ float4 colb[64];
    __shared__ float  colp[64];
    __shared__ unsigned long long s_or;
    __shared__ int s_last;

    int rowlim = (bx + 1) * 64;
    if (!done && by * 2048 < rowlim) {
        if (t == 0) s_or = 0ull;
        if (t < 64) {
            int j = bx * 64 + t;
            colb[t] = make_float4(g_y1[j], g_x1[j], g_y2[j], g_x2[j]);
            colp[t] = g_pa[j];
        }
        __syncthreads();
        int basesup = (bx & ~3) * 64;
        unsigned long long orloc = 0ull;
        for (int k = 0; k < 8; k++) {
            int i = by * 2048 + k * 256 + t;
            if (i >= rowlim) break;
            float y1 = g_y1[i], x1 = g_x1[i], y2 = g_y2[i], x2 = g_x2[i];
            float pa = g_pa[i];
            unsigned long long m = 0ull;
            int c0 = i - bx * 64 + 1;
            if (c0 <= 0) {
#pragma unroll 16
                for (int cc = 0; cc < 64; cc++) {
                    float4 cb = colb[cc];
                    float iy1 = fmaxf(y1, cb.x), ix1 = fmaxf(x1, cb.y);
                    float iy2 = fminf(y2, cb.z), ix2 = fminf(x2, cb.w);
                    float dy = fmaxf(iy2 - iy1, 0.f), dx = fmaxf(ix2 - ix1, 0.f);
                    bool cond = fmaf(1.7f, dy * dx, -pa) > colp[cc];
                    m |= ((unsigned long long)cond) << cc;
                }
            } else {
                for (int cc = c0; cc < 64; cc++) {
                    float4 cb = colb[cc];
                    float iy1 = fmaxf(y1, cb.x), ix1 = fmaxf(x1, cb.y);
                    float iy2 = fminf(y2, cb.z), ix2 = fminf(x2, cb.w);
                    float dy = fmaxf(iy2 - iy1, 0.f), dx = fmaxf(ix2 - ix1, 0.f);
                    bool cond = fmaf(1.7f, dy * dx, -pa) > colp[cc];
                    m |= ((unsigned long long)cond) << cc;
                }
            }
            g_maskT[bx][i] = m;
            if (m && i < basesup) orloc |= m;
        }
        if (orloc) atomicOr(&s_or, orloc);
        __syncthreads();
        if (t == 0 && s_or) atomicOr(&g_colORall[bx], s_or);
    }
    __threadfence();
    __syncthreads();
    if (t == 0) s_last = (atomicAdd(&g_mcount1, 1) == total - 1);
    __syncthreads();
    if (!s_last) return;

    if (!done && !(*(volatile int*)&g_done))
        nms_run(G1, NB, out, /*do_wait=*/0);

    // reset state for the next graph replay
    __syncthreads();
    bool ok = (g_nstash >= NPRE && g_nstash <= STASH_CAP);
    for (int i = t; i < NB; i += 256) { g_alive[i] = 0ull; g_colORall[i] = 0ull; }
    if (t < 16) g_supcnt[t] = 0;
    if (t < NBKT) g_bcnt[t] = 0;
    if (!ok) for (int i = t; i < HB; i += 256) g_hist[i] = 0u;
    __syncthreads();
    if (t == 0) {
        g_kcount = 0; g_done = 0; g_nstash = 0;
        g_mcount1 = 0; g_ndead = 0; g_ndovf = 0;
    }
}

// ---------------- launch ----------------------------------------------------
extern "C" void kernel_launch(void* const* d_in, const int* in_sizes, int n_in,
                              void* d_out, int out_size) {
    const float* enc    = (const float*)d_in[0];  // encoded_bboxes [N,4]
    const float* anch   = (const float*)d_in[1];  // anchors        [N,4]
    const float* scores = (const float*)d_in[2];  // scores         [N]
    float* out = (float*)d_out;                   // 2000*4 boxes + 2000 scores
    int n = in_sizes[2];
    int n4 = n / 4;

    scan_stash_k<<<1024, 256>>>((const float4*)scores, n4);
    sortdecode_k<<<NBKT, 256>>>(enc, anch, scores, n);

    // chunk 1: overlapped producers + consumer (block 0 = NMS)
    masknms1_k<<<NTILE1 + 1, 256>>>(out);

    // chunk 2: fallback for exit > G1; usually ghost; resets state
    {
        dim3 grid(NB - G1, 3);                      // 8 row-tiles per block
        masknms2_k<<<grid, 256>>>(grid.x * grid.y, out);
    }
}